// round 7
// baseline (speedup 1.0000x reference)
#include <cuda_runtime.h>
#include <cuda_fp16.h>
#include <cstdint>
#include <math.h>

// Problem constants
#define NB 64
#define NSX 128
#define NT 128
#define NE 128
#define NH 256
#define NV 32000
#define G4 1024

// ---------------- device scratch ----------------
__device__ float  g_xg[8192 * G4];          // x-gates fp32 (32 MB)
__device__ __half g_xh[8192 * NE];          // fp16 embedded inputs
__device__ __half g_yh[8192 * NH];          // fp16 layer outputs
__device__ float  g_hF[2 * NB * NH];
__device__ float  g_cF[2 * NB * NH];
__device__ __half g_w0[G4 * NE];            // enc Wih0 fp16
__device__ __half g_w1[G4 * NH];            // enc Wih1
__device__ __half g_w2[G4 * NE];            // dec Wih0
__device__ __half g_w3[G4 * NH];            // dec Wih1
__device__ __half g_fw[NV * NH];            // fc_W fp16

// ---------------- small helpers ----------------
__device__ __forceinline__ uint32_t smem_u32(const void* p) {
    uint32_t a;
    asm("{ .reg .u64 t; cvta.to.shared.u64 t, %1; cvt.u32.u64 %0, t; }"
        : "=r"(a) : "l"(p));
    return a;
}
__device__ __forceinline__ void cp16(uint32_t dst, const void* src) {
    asm volatile("cp.async.cg.shared.global [%0], [%1], 16;" :: "r"(dst), "l"(src));
}
__device__ __forceinline__ void ldsm4(uint32_t& r0, uint32_t& r1, uint32_t& r2,
                                      uint32_t& r3, uint32_t addr) {
    asm volatile("ldmatrix.sync.aligned.m8n8.x4.shared.b16 {%0,%1,%2,%3}, [%4];"
                 : "=r"(r0), "=r"(r1), "=r"(r2), "=r"(r3) : "r"(addr));
}
__device__ __forceinline__ void mma16816(float* c, const uint32_t* a,
                                         uint32_t b0, uint32_t b1) {
    asm volatile(
        "mma.sync.aligned.m16n8k16.row.col.f32.f16.f16.f32 "
        "{%0,%1,%2,%3}, {%4,%5,%6,%7}, {%8,%9}, {%0,%1,%2,%3};"
        : "+f"(c[0]), "+f"(c[1]), "+f"(c[2]), "+f"(c[3])
        : "r"(a[0]), "r"(a[1]), "r"(a[2]), "r"(a[3]), "r"(b0), "r"(b1));
}
// packed f32x2 helpers (base sm_100+ PTX, arch-family stable)
__device__ __forceinline__ uint64_t pack2(float w) {
    uint64_t r;
    asm("mov.b64 %0, {%1, %1};" : "=l"(r) : "f"(w));
    return r;
}
__device__ __forceinline__ void ffma2(uint64_t& acc, uint64_t h, uint64_t w) {
    asm("fma.rn.f32x2 %0, %1, %2, %0;" : "+l"(acc) : "l"(h), "l"(w));
}
__device__ __forceinline__ void unpack2(uint64_t v, float& lo, float& hi) {
    asm("mov.b64 {%0, %1}, %2;" : "=f"(lo), "=f"(hi) : "l"(v));
}

// ---------------- fused conversion kernel ----------------
// segments (float4-granular): [0,131072) eWih0->w0, [..,393216) eWih1->w1,
// [..,524288) dWih0->w2, [..,786432) dWih1->w3, [..,8978432) fcW->fw
__global__ void f2h_all_kernel(const float* __restrict__ e0, const float* __restrict__ e1,
                               const float* __restrict__ q0, const float* __restrict__ q1,
                               const float* __restrict__ fw,
                               __half* __restrict__ w0, __half* __restrict__ w1,
                               __half* __restrict__ w2, __half* __restrict__ w3,
                               __half* __restrict__ wf) {
    int i = (blockIdx.x * blockDim.x + threadIdx.x) * 4;
    const float* s; __half* d; int off;
    if (i < 131072)      { s = e0; d = w0; off = i; }
    else if (i < 393216) { s = e1; d = w1; off = i - 131072; }
    else if (i < 524288) { s = q0; d = w2; off = i - 393216; }
    else if (i < 786432) { s = q1; d = w3; off = i - 524288; }
    else                 { s = fw; d = wf; off = i - 786432;
                           if (off >= 8192000) return; }
    float4 v = *(const float4*)(s + off);
    __half2* o = (__half2*)(d + off);
    o[0] = __floats2half2_rn(v.x, v.y);
    o[1] = __floats2half2_rn(v.z, v.w);
}

// ---------------- embedding kernels ----------------
__global__ void embed_src_kernel(const int* __restrict__ src,
                                 const float* __restrict__ emb,
                                 __half* __restrict__ out) {
    int idx = blockIdx.x * blockDim.x + threadIdx.x;
    if (idx >= NSX * NB * NE) return;
    int e = idx % NE;
    int r = idx / NE;
    int b = r % NB;
    int s = r / NB;
    out[(size_t)r * NE + e] = __float2half(emb[(size_t)src[b * NSX + s] * NE + e]);
}

__global__ void embed_trg_kernel(const int* __restrict__ trg,
                                 const float* __restrict__ emb,
                                 __half* __restrict__ out) {
    int idx = blockIdx.x * blockDim.x + threadIdx.x;
    if (idx >= 127 * NB * NE) return;
    int e = idx % NE;
    int r = idx / NE;
    int b = r % NB;
    int t = r / NB;
    int tok = (t == 0) ? 1 : trg[b * NT + t];
    out[(size_t)r * NE + e] = __float2half(emb[(size_t)tok * NE + e]);
}

__global__ void zero_first_kernel(float* __restrict__ out) {
    int idx = blockIdx.x * blockDim.x + threadIdx.x;
    if (idx >= NB * NV) return;
    int v = idx % NV;
    int b = idx / NV;
    out[(size_t)b * NT * NV + v] = 0.f;
}

// ---------------- fp16 tensor-core GEMM (128x256 block, 64x64 warp tiles) ----------------
#define GSTAGE 49152                  // A 16KB + B 32KB
#define GSMEM  (3 * GSTAGE)

__global__ void __launch_bounds__(256, 1)
gemm16_kernel(const __half* __restrict__ A, const __half* __restrict__ W,
              const float* __restrict__ b0, const float* __restrict__ b1,
              float* __restrict__ C, int N, int K, int fcMode) {
    extern __shared__ char smbuf[];
    const uint32_t sb = smem_u32(smbuf);
    const int tid = threadIdx.x;
    const int lane = tid & 31;
    const int wid = tid >> 5;
    const int warp_m = wid & 1;
    const int warp_n = wid >> 1;
    const int m0 = blockIdx.y * 128;
    const int n0 = blockIdx.x * 256;
    const int KT = K >> 6;

    float acc[4][8][4];
#pragma unroll
    for (int i = 0; i < 4; i++)
#pragma unroll
        for (int j = 0; j < 8; j++)
#pragma unroll
            for (int q = 0; q < 4; q++) acc[i][j][q] = 0.f;

    auto loadStage = [&](int kt, int s) {
        const uint32_t st = sb + (uint32_t)s * GSTAGE;
        const __half* Ag = A + (size_t)m0 * K + kt * 64;
        const __half* Wg = W + (size_t)n0 * K + kt * 64;
#pragma unroll
        for (int i = 0; i < 4; i++) {
            int idx = i * 256 + tid;
            int row = idx >> 3, c = idx & 7;
            uint32_t off = (uint32_t)(row * 128 + ((c ^ (row & 7)) << 4));
            cp16(st + off, Ag + (size_t)row * K + c * 8);
        }
#pragma unroll
        for (int i = 0; i < 8; i++) {
            int idx = i * 256 + tid;
            int row = idx >> 3, c = idx & 7;
            uint32_t off = (uint32_t)(row * 128 + ((c ^ (row & 7)) << 4));
            cp16(st + 16384 + off, Wg + (size_t)row * K + c * 8);
        }
        asm volatile("cp.async.commit_group;" ::: "memory");
    };

    loadStage(0, 0);
    loadStage(1, 1);
    asm volatile("cp.async.wait_group 1;" ::: "memory");
    __syncthreads();

    for (int kt = 0; kt < KT; kt++) {
        const int s = kt % 3;
        if (kt + 2 < KT) loadStage(kt + 2, (kt + 2) % 3);
        const uint32_t stA = sb + (uint32_t)s * GSTAGE;
        const uint32_t stB = stA + 16384;
#pragma unroll
        for (int k16 = 0; k16 < 4; k16++) {
            uint32_t a[4][4];
#pragma unroll
            for (int mt = 0; mt < 4; mt++) {
                int row = warp_m * 64 + mt * 16 + (lane & 15);
                int ch = k16 * 2 + (lane >> 4);
                ldsm4(a[mt][0], a[mt][1], a[mt][2], a[mt][3],
                      stA + row * 128 + ((ch ^ (row & 7)) << 4));
            }
#pragma unroll
            for (int p = 0; p < 4; p++) {
                int nrow = warp_n * 64 + p * 16 + ((lane >> 4) & 1) * 8 + (lane & 7);
                int ch = k16 * 2 + ((lane >> 3) & 1);
                uint32_t br0, br1, br2, br3;
                ldsm4(br0, br1, br2, br3,
                      stB + nrow * 128 + ((ch ^ (nrow & 7)) << 4));
#pragma unroll
                for (int mt = 0; mt < 4; mt++) {
                    mma16816(acc[mt][2 * p],     a[mt], br0, br1);
                    mma16816(acc[mt][2 * p + 1], a[mt], br2, br3);
                }
            }
        }
        asm volatile("cp.async.wait_group 1;" ::: "memory");
        __syncthreads();
    }

    const int lrow = lane >> 2;
    const int lcol = (lane & 3) * 2;
#pragma unroll
    for (int nt = 0; nt < 8; nt++) {
        const int n = n0 + warp_n * 64 + nt * 8 + lcol;
        float bv0 = b0 ? b0[n] : 0.f;
        float bv1 = b0 ? b0[n + 1] : 0.f;
        if (b1) { bv0 += b1[n]; bv1 += b1[n + 1]; }
#pragma unroll
        for (int mt = 0; mt < 4; mt++) {
            const int mbase = m0 + warp_m * 64 + mt * 16 + lrow;
#pragma unroll
            for (int half = 0; half < 2; half++) {
                const int m = mbase + half * 8;
                float2 v;
                v.x = acc[mt][nt][half * 2 + 0] + bv0;
                v.y = acc[mt][nt][half * 2 + 1] + bv1;
                if (fcMode) {
                    if (m < 8128) {
                        int t = m >> 6, b = m & 63;
                        *(float2*)(C + ((size_t)(b * 128 + t + 1)) * NV + n) = v;
                    }
                } else {
                    *(float2*)(C + (size_t)m * N + n) = v;
                }
            }
        }
    }
}

// ---------------- clustered persistent LSTM recurrence (reg-weights + f32x2) ----------------
// 16 clusters x 8 CTAs; cluster owns 4 batches, CTA rank = 32-gate-col slice.
// Weights live in registers (128/thread). h tile stored transposed [k][b] so
// batch pairs load as one LDS.64 broadcast feeding packed f32x2 FMAs.
#define REC_SMEM_FLOATS (256 * 129 + 2 * 1024 + 256 * 17)
#define REC_SMEM_BYTES  (REC_SMEM_FLOATS * 4)

__global__ void __cluster_dims__(8, 1, 1) __launch_bounds__(256, 1)
lstm_rec_kernel(const float* __restrict__ xg,
                const float* __restrict__ Whh,
                const float* __restrict__ hInit,
                const float* __restrict__ cInit,
                __half* __restrict__ ysh,
                float* __restrict__ hFin,
                float* __restrict__ cFin,
                int nSteps) {
    extern __shared__ float smf[];
    float* Wsl = smf;                      // 256*129 staging (init only)
    float* hs0 = Wsl + 256 * 129;          // 1024, layout [k*4 + b]
    float* hs1 = hs0 + 1024;
    float* red = hs1 + 1024;               // 256*17

    const int tid = threadIdx.x;
    uint32_t rank;
    asm("mov.u32 %0, %%cluster_ctarank;" : "=r"(rank));
    const int bt = blockIdx.x >> 3;
    const int n0 = (int)rank * 32;
    const int ks = tid >> 5;
    const int nl = tid & 31;

    // stage Whh slice coalesced: Wsl[k*129 + g*32+j] = Whh[g*256+n0+j][k]
    for (int j = 0; j < 128; j++) {
        Wsl[tid * 129 + j] =
            Whh[(size_t)((j >> 5) * 256 + n0 + (j & 31)) * 256 + tid];
    }
    __syncthreads();

    // per-thread weights into registers: wreg[g*32+kk] = W[g*256+n0+nl][ks*32+kk]
    float wreg[128];
#pragma unroll
    for (int g = 0; g < 4; g++)
#pragma unroll
        for (int kk = 0; kk < 32; kk++)
            wreg[g * 32 + kk] = Wsl[(ks * 32 + kk) * 129 + g * 32 + nl];

    const int fb = tid >> 5;               // finalize threads (tid<128)
    const int fn = tid & 31;
    const int bG = bt * 4 + fb;
    float cS = 0.f;
    if (tid < 128 && cInit) cS = cInit[bG * 256 + n0 + fn];

    // init h buffer 0 (transposed [k][b])
    for (int i = tid; i < 1024; i += 256) {
        int k = i >> 2, b = i & 3;
        hs0[i] = hInit ? hInit[(size_t)(bt * 4 + b) * 256 + k] : 0.f;
    }

    // remote DSMEM addrs of this thread's h slot: [ (n0+fn)*4 + fb ]
    uint32_t remA[8], remB[8];
    if (tid < 128) {
        uint32_t offs = (uint32_t)((n0 + fn) * 4 + fb) * 4;
        uint32_t la = smem_u32(hs0) + offs;
        uint32_t lb = smem_u32(hs1) + offs;
#pragma unroll
        for (int r = 0; r < 8; r++) {
            asm("mapa.shared::cluster.u32 %0, %1, %2;" : "=r"(remA[r]) : "r"(la), "r"(r));
            asm("mapa.shared::cluster.u32 %0, %1, %2;" : "=r"(remB[r]) : "r"(lb), "r"(r));
        }
    }
    __syncthreads();
    asm volatile("barrier.cluster.arrive.aligned;" ::: "memory");
    asm volatile("barrier.cluster.wait.aligned;" ::: "memory");

    int p = 0;
    for (int step = 0; step < nSteps; step++) {
        // xg prefetch (overlaps matvec)
        float gi = 0.f, gf = 0.f, gg = 0.f, go = 0.f;
        size_t row = 0;
        if (tid < 128) {
            row = (size_t)step * 64 + bG;
            const float* xr = xg + row * 1024 + n0 + fn;
            gi = xr[0]; gf = xr[256]; gg = xr[512]; go = xr[768];
        }

        const float* hcur = p ? hs1 : hs0;
        const uint64_t* hp = (const uint64_t*)hcur + (size_t)ks * 64;

        uint64_t a01[4] = {0, 0, 0, 0};
        uint64_t a23[4] = {0, 0, 0, 0};
#pragma unroll
        for (int kk = 0; kk < 32; kk++) {
            uint64_t b01 = hp[kk * 2];
            uint64_t b23 = hp[kk * 2 + 1];
#pragma unroll
            for (int g = 0; g < 4; g++) {
                uint64_t wp = pack2(wreg[g * 32 + kk]);
                ffma2(a01[g], b01, wp);
                ffma2(a23[g], b23, wp);
            }
        }
        {
            float* rp = red + tid * 17;
#pragma unroll
            for (int g = 0; g < 4; g++) {
                float l0, h0, l1, h1;
                unpack2(a01[g], l0, h0);
                unpack2(a23[g], l1, h1);
                rp[0 * 4 + g] = l0;
                rp[1 * 4 + g] = h0;
                rp[2 * 4 + g] = l1;
                rp[3 * 4 + g] = h1;
            }
        }
        __syncthreads();

        float h = 0.f;
        if (tid < 128) {
#pragma unroll
            for (int q = 0; q < 8; q++) {
                const float* rq = red + (q * 32 + fn) * 17 + fb * 4;
                gi += rq[0]; gf += rq[1]; gg += rq[2]; go += rq[3];
            }
            float iv = 1.f / (1.f + expf(-gi));
            float fv = 1.f / (1.f + expf(-gf));
            float gv = tanhf(gg);
            float ov = 1.f / (1.f + expf(-go));
            cS = fv * cS + iv * gv;
            h = ov * tanhf(cS);

            uint32_t hb = __float_as_uint(h);
#pragma unroll
            for (int r = 0; r < 8; r++) {
                uint32_t ra = p ? remA[r] : remB[r];   // write buffer p^1
                asm volatile("st.shared::cluster.u32 [%0], %1;" :: "r"(ra), "r"(hb));
            }
        }

        asm volatile("barrier.cluster.arrive.aligned;" ::: "memory");
        if (tid < 128) {
            if (ysh) ysh[row * 256 + n0 + fn] = __float2half(h);
            if (step == nSteps - 1) {
                if (hFin) hFin[bG * 256 + n0 + fn] = h;
                if (cFin) cFin[bG * 256 + n0 + fn] = cS;
            }
        }
        asm volatile("barrier.cluster.wait.aligned;" ::: "memory");
        p ^= 1;
    }
}

// ---------------- host launch ----------------
extern "C" void kernel_launch(void* const* d_in, const int* in_sizes, int n_in,
                              void* d_out, int out_size) {
    const int*   src     = (const int*)d_in[0];
    const int*   trg     = (const int*)d_in[1];
    const float* enc_emb = (const float*)d_in[2];
    const float* dec_emb = (const float*)d_in[3];
    const float* eWih0 = (const float*)d_in[4],  *eWhh0 = (const float*)d_in[5];
    const float* ebih0 = (const float*)d_in[6],  *ebhh0 = (const float*)d_in[7];
    const float* eWih1 = (const float*)d_in[8],  *eWhh1 = (const float*)d_in[9];
    const float* ebih1 = (const float*)d_in[10], *ebhh1 = (const float*)d_in[11];
    const float* dWih0 = (const float*)d_in[12], *dWhh0 = (const float*)d_in[13];
    const float* dbih0 = (const float*)d_in[14], *dbhh0 = (const float*)d_in[15];
    const float* dWih1 = (const float*)d_in[16], *dWhh1 = (const float*)d_in[17];
    const float* dbih1 = (const float*)d_in[18], *dbhh1 = (const float*)d_in[19];
    const float* fcW   = (const float*)d_in[20], *fcb   = (const float*)d_in[21];
    float* out = (float*)d_out;

    float *pxg, *phF, *pcF;
    __half *pxh, *pyh, *pw0, *pw1, *pw2, *pw3, *pfw;
    cudaGetSymbolAddress((void**)&pxg,   g_xg);
    cudaGetSymbolAddress((void**)&phF,   g_hF);
    cudaGetSymbolAddress((void**)&pcF,   g_cF);
    cudaGetSymbolAddress((void**)&pxh,   g_xh);
    cudaGetSymbolAddress((void**)&pyh,   g_yh);
    cudaGetSymbolAddress((void**)&pw0,   g_w0);
    cudaGetSymbolAddress((void**)&pw1,   g_w1);
    cudaGetSymbolAddress((void**)&pw2,   g_w2);
    cudaGetSymbolAddress((void**)&pw3,   g_w3);
    cudaGetSymbolAddress((void**)&pfw,   g_fw);

    cudaFuncSetAttribute(lstm_rec_kernel,
                         cudaFuncAttributeMaxDynamicSharedMemorySize, REC_SMEM_BYTES);
    cudaFuncSetAttribute(gemm16_kernel,
                         cudaFuncAttributeMaxDynamicSharedMemorySize, GSMEM);

    // fused weight conversion + output-row-0 zeroing
    f2h_all_kernel<<<(8978432 / 4 + 255) / 256, 256>>>(eWih0, eWih1, dWih0, dWih1, fcW,
                                                       pw0, pw1, pw2, pw3, pfw);
    zero_first_kernel<<<(NB * NV + 255) / 256, 256>>>(out);

    // ---- Encoder ----
    embed_src_kernel<<<(NSX * NB * NE + 255) / 256, 256>>>(src, enc_emb, pxh);
    gemm16_kernel<<<dim3(4, 64), 256, GSMEM>>>(pxh, pw0, ebih0, ebhh0, pxg,
                                               G4, NE, 0);
    lstm_rec_kernel<<<128, 256, REC_SMEM_BYTES>>>(pxg, eWhh0, nullptr, nullptr,
                                                  pyh, phF, pcF, 128);
    gemm16_kernel<<<dim3(4, 64), 256, GSMEM>>>(pyh, pw1, ebih1, ebhh1, pxg,
                                               G4, NH, 0);
    lstm_rec_kernel<<<128, 256, REC_SMEM_BYTES>>>(pxg, eWhh1, nullptr, nullptr,
                                                  nullptr, phF + NB * NH, pcF + NB * NH,
                                                  128);

    // ---- Decoder (teacher forced) ----
    embed_trg_kernel<<<(127 * NB * NE + 255) / 256, 256>>>(trg, dec_emb, pxh);
    gemm16_kernel<<<dim3(4, 64), 256, GSMEM>>>(pxh, pw2, dbih0, dbhh0, pxg,
                                               G4, NE, 0);
    lstm_rec_kernel<<<128, 256, REC_SMEM_BYTES>>>(pxg, dWhh0, phF, pcF,
                                                  pyh, nullptr, nullptr, 127);
    gemm16_kernel<<<dim3(4, 64), 256, GSMEM>>>(pyh, pw3, dbih1, dbhh1, pxg,
                                               G4, NH, 0);
    lstm_rec_kernel<<<128, 256, REC_SMEM_BYTES>>>(pxg, dWhh1, phF + NB * NH, pcF + NB * NH,
                                                  pyh, nullptr, nullptr, 127);

    // ---- Output: fp16 tensor-core FC over all steps ----
    gemm16_kernel<<<dim3(125, 64), 256, GSMEM>>>(pyh, pfw, fcb, nullptr, out,
                                                 NV, NH, 1);
}

// round 8
// speedup vs baseline: 1.0429x; 1.0429x over previous
#include <cuda_runtime.h>
#include <cuda_fp16.h>
#include <cstdint>
#include <math.h>

// Problem constants
#define NB 64
#define NSX 128
#define NT 128
#define NE 128
#define NH 256
#define NV 32000
#define G4 1024

// ---------------- device scratch ----------------
__device__ float  g_xg[8192 * G4];          // x-gates fp32 (32 MB)
__device__ __half g_xh[8192 * NE];          // fp16 embedded inputs
__device__ __half g_yh[8192 * NH];          // fp16 layer outputs
__device__ float  g_hF[2 * NB * NH];
__device__ float  g_cF[2 * NB * NH];
__device__ __half g_w0[G4 * NE];            // enc Wih0 fp16
__device__ __half g_w1[G4 * NH];            // enc Wih1
__device__ __half g_w2[G4 * NE];            // dec Wih0
__device__ __half g_w3[G4 * NH];            // dec Wih1
__device__ __half g_fw[NV * NH];            // fc_W fp16

// ---------------- small helpers ----------------
__device__ __forceinline__ uint32_t smem_u32(const void* p) {
    uint32_t a;
    asm("{ .reg .u64 t; cvta.to.shared.u64 t, %1; cvt.u32.u64 %0, t; }"
        : "=r"(a) : "l"(p));
    return a;
}
__device__ __forceinline__ void cp16(uint32_t dst, const void* src) {
    asm volatile("cp.async.cg.shared.global [%0], [%1], 16;" :: "r"(dst), "l"(src));
}
__device__ __forceinline__ void ldsm4(uint32_t& r0, uint32_t& r1, uint32_t& r2,
                                      uint32_t& r3, uint32_t addr) {
    asm volatile("ldmatrix.sync.aligned.m8n8.x4.shared.b16 {%0,%1,%2,%3}, [%4];"
                 : "=r"(r0), "=r"(r1), "=r"(r2), "=r"(r3) : "r"(addr));
}
__device__ __forceinline__ void mma16816(float* c, const uint32_t* a,
                                         uint32_t b0, uint32_t b1) {
    asm volatile(
        "mma.sync.aligned.m16n8k16.row.col.f32.f16.f16.f32 "
        "{%0,%1,%2,%3}, {%4,%5,%6,%7}, {%8,%9}, {%0,%1,%2,%3};"
        : "+f"(c[0]), "+f"(c[1]), "+f"(c[2]), "+f"(c[3])
        : "r"(a[0]), "r"(a[1]), "r"(a[2]), "r"(a[3]), "r"(b0), "r"(b1));
}

// ---------------- fused conversion kernel ----------------
__global__ void f2h_all_kernel(const float* __restrict__ e0, const float* __restrict__ e1,
                               const float* __restrict__ q0, const float* __restrict__ q1,
                               const float* __restrict__ fw,
                               __half* __restrict__ w0, __half* __restrict__ w1,
                               __half* __restrict__ w2, __half* __restrict__ w3,
                               __half* __restrict__ wf) {
    int i = (blockIdx.x * blockDim.x + threadIdx.x) * 4;
    const float* s; __half* d; int off;
    if (i < 131072)      { s = e0; d = w0; off = i; }
    else if (i < 393216) { s = e1; d = w1; off = i - 131072; }
    else if (i < 524288) { s = q0; d = w2; off = i - 393216; }
    else if (i < 786432) { s = q1; d = w3; off = i - 524288; }
    else                 { s = fw; d = wf; off = i - 786432;
                           if (off >= 8192000) return; }
    float4 v = *(const float4*)(s + off);
    __half2* o = (__half2*)(d + off);
    o[0] = __floats2half2_rn(v.x, v.y);
    o[1] = __floats2half2_rn(v.z, v.w);
}

// ---------------- embedding kernels ----------------
__global__ void embed_src_kernel(const int* __restrict__ src,
                                 const float* __restrict__ emb,
                                 __half* __restrict__ out) {
    int idx = blockIdx.x * blockDim.x + threadIdx.x;
    if (idx >= NSX * NB * NE) return;
    int e = idx % NE;
    int r = idx / NE;
    int b = r % NB;
    int s = r / NB;
    out[(size_t)r * NE + e] = __float2half(emb[(size_t)src[b * NSX + s] * NE + e]);
}

__global__ void embed_trg_kernel(const int* __restrict__ trg,
                                 const float* __restrict__ emb,
                                 __half* __restrict__ out) {
    int idx = blockIdx.x * blockDim.x + threadIdx.x;
    if (idx >= 127 * NB * NE) return;
    int e = idx % NE;
    int r = idx / NE;
    int b = r % NB;
    int t = r / NB;
    int tok = (t == 0) ? 1 : trg[b * NT + t];
    out[(size_t)r * NE + e] = __float2half(emb[(size_t)tok * NE + e]);
}

__global__ void zero_first_kernel(float* __restrict__ out) {
    int idx = blockIdx.x * blockDim.x + threadIdx.x;
    if (idx >= NB * NV) return;
    int v = idx % NV;
    int b = idx / NV;
    out[(size_t)b * NT * NV + v] = 0.f;
}

// ---------------- fp16 tensor-core GEMM ----------------
// Block tile 128(M) x 256(N), BK=64, 512 threads = 16 warps = 4(M)x4(N),
// warp tile 32x64. 3-stage cp.async pipeline (48KB/stage).
// fcMode: logical row m = t*64+b -> C[(b*128 + t + 1)*NV + n], skip m >= 8128.
#define GSTAGE 49152                  // A 16KB + B 32KB
#define GSMEM  (3 * GSTAGE)

__global__ void __launch_bounds__(512, 1)
gemm16_kernel(const __half* __restrict__ A, const __half* __restrict__ W,
              const float* __restrict__ b0, const float* __restrict__ b1,
              float* __restrict__ C, int N, int K, int fcMode) {
    extern __shared__ char smbuf[];
    const uint32_t sb = smem_u32(smbuf);
    const int tid = threadIdx.x;
    const int lane = tid & 31;
    const int wid = tid >> 5;         // 0..15
    const int warp_m = wid & 3;       // 4 warps over M (32 rows each)
    const int warp_n = wid >> 2;      // 4 warps over N (64 cols each)
    const int m0 = blockIdx.y * 128;
    const int n0 = blockIdx.x * 256;
    const int KT = K >> 6;            // 2 or 4

    float acc[2][8][4];
#pragma unroll
    for (int i = 0; i < 2; i++)
#pragma unroll
        for (int j = 0; j < 8; j++)
#pragma unroll
            for (int q = 0; q < 4; q++) acc[i][j][q] = 0.f;

    auto loadStage = [&](int kt, int s) {
        const uint32_t st = sb + (uint32_t)s * GSTAGE;
        const __half* Ag = A + (size_t)m0 * K + kt * 64;
        const __half* Wg = W + (size_t)n0 * K + kt * 64;
#pragma unroll
        for (int i = 0; i < 2; i++) {            // A: 1024 16B-chunks
            int idx = i * 512 + tid;
            int row = idx >> 3, c = idx & 7;
            uint32_t off = (uint32_t)(row * 128 + ((c ^ (row & 7)) << 4));
            cp16(st + off, Ag + (size_t)row * K + c * 8);
        }
#pragma unroll
        for (int i = 0; i < 4; i++) {            // B: 2048 16B-chunks
            int idx = i * 512 + tid;
            int row = idx >> 3, c = idx & 7;
            uint32_t off = (uint32_t)(row * 128 + ((c ^ (row & 7)) << 4));
            cp16(st + 16384 + off, Wg + (size_t)row * K + c * 8);
        }
        asm volatile("cp.async.commit_group;" ::: "memory");
    };

    loadStage(0, 0);
    loadStage(1, 1);
    asm volatile("cp.async.wait_group 1;" ::: "memory");
    __syncthreads();

    for (int kt = 0; kt < KT; kt++) {
        const int s = kt % 3;
        if (kt + 2 < KT) loadStage(kt + 2, (kt + 2) % 3);
        const uint32_t stA = sb + (uint32_t)s * GSTAGE;
        const uint32_t stB = stA + 16384;
#pragma unroll
        for (int k16 = 0; k16 < 4; k16++) {
            uint32_t a[2][4];
#pragma unroll
            for (int mt = 0; mt < 2; mt++) {
                int row = warp_m * 32 + mt * 16 + (lane & 15);
                int ch = k16 * 2 + (lane >> 4);
                ldsm4(a[mt][0], a[mt][1], a[mt][2], a[mt][3],
                      stA + row * 128 + ((ch ^ (row & 7)) << 4));
            }
#pragma unroll
            for (int p = 0; p < 4; p++) {
                int nrow = warp_n * 64 + p * 16 + ((lane >> 4) & 1) * 8 + (lane & 7);
                int ch = k16 * 2 + ((lane >> 3) & 1);
                uint32_t br0, br1, br2, br3;
                ldsm4(br0, br1, br2, br3,
                      stB + nrow * 128 + ((ch ^ (nrow & 7)) << 4));
#pragma unroll
                for (int mt = 0; mt < 2; mt++) {
                    mma16816(acc[mt][2 * p],     a[mt], br0, br1);
                    mma16816(acc[mt][2 * p + 1], a[mt], br2, br3);
                }
            }
        }
        asm volatile("cp.async.wait_group 1;" ::: "memory");
        __syncthreads();
    }

    // ---- epilogue ----
    const int lrow = lane >> 2;
    const int lcol = (lane & 3) * 2;
#pragma unroll
    for (int nt = 0; nt < 8; nt++) {
        const int n = n0 + warp_n * 64 + nt * 8 + lcol;
        float bv0 = b0 ? b0[n] : 0.f;
        float bv1 = b0 ? b0[n + 1] : 0.f;
        if (b1) { bv0 += b1[n]; bv1 += b1[n + 1]; }
#pragma unroll
        for (int mt = 0; mt < 2; mt++) {
            const int mbase = m0 + warp_m * 32 + mt * 16 + lrow;
#pragma unroll
            for (int half = 0; half < 2; half++) {
                const int m = mbase + half * 8;
                float2 v;
                v.x = acc[mt][nt][half * 2 + 0] + bv0;
                v.y = acc[mt][nt][half * 2 + 1] + bv1;
                if (fcMode) {
                    if (m < 8128) {
                        int t = m >> 6, b = m & 63;
                        *(float2*)(C + ((size_t)(b * 128 + t + 1)) * NV + n) = v;
                    }
                } else {
                    *(float2*)(C + (size_t)m * N + n) = v;
                }
            }
        }
    }
}

// ---------------- clustered persistent LSTM recurrence (R6 version) ----------------
#define REC_SMEM_FLOATS (256 * 129 + 2 * 1024 + 8 * 32 * 17)
#define REC_SMEM_BYTES  (REC_SMEM_FLOATS * 4)

__global__ void __cluster_dims__(8, 1, 1) __launch_bounds__(256, 1)
lstm_rec_kernel(const float* __restrict__ xg,
                const float* __restrict__ Whh,
                const float* __restrict__ hInit,
                const float* __restrict__ cInit,
                __half* __restrict__ ysh,
                float* __restrict__ hFin,
                float* __restrict__ cFin,
                int nSteps) {
    extern __shared__ float smf[];
    float* Wsl = smf;                      // 256*129
    float* hs0 = Wsl + 256 * 129;          // 1024 (buffer 0)
    float* hs1 = hs0 + 1024;               // 1024 (buffer 1)
    float* red = hs1 + 1024;               // 256*17

    const int tid = threadIdx.x;
    uint32_t rank;
    asm("mov.u32 %0, %%cluster_ctarank;" : "=r"(rank));
    const int bt = blockIdx.x >> 3;
    const int n0 = (int)rank * 32;
    const int ks = tid >> 5;
    const int nl = tid & 31;

    for (int j = 0; j < 128; j++) {
        Wsl[tid * 129 + j] =
            Whh[(size_t)((j >> 5) * 256 + n0 + (j & 31)) * 256 + tid];
    }

    const int fb = tid >> 5;
    const int fn = tid & 31;
    const int bG = bt * 4 + fb;
    float cS = 0.f;
    if (tid < 128 && cInit) cS = cInit[bG * 256 + n0 + fn];

    if (hInit)
        ((float4*)hs0)[tid] = ((const float4*)(hInit + (size_t)bt * 4 * 256))[tid];
    else
        ((float4*)hs0)[tid] = make_float4(0.f, 0.f, 0.f, 0.f);

    uint32_t remA[8], remB[8];
    if (tid < 128) {
        uint32_t offs = (uint32_t)(fb * 256 + n0 + fn) * 4;
        uint32_t la = smem_u32(hs0) + offs;
        uint32_t lb = smem_u32(hs1) + offs;
#pragma unroll
        for (int r = 0; r < 8; r++) {
            asm("mapa.shared::cluster.u32 %0, %1, %2;" : "=r"(remA[r]) : "r"(la), "r"(r));
            asm("mapa.shared::cluster.u32 %0, %1, %2;" : "=r"(remB[r]) : "r"(lb), "r"(r));
        }
    }
    __syncthreads();
    asm volatile("barrier.cluster.arrive.aligned;" ::: "memory");
    asm volatile("barrier.cluster.wait.aligned;" ::: "memory");

    int p = 0;
    for (int step = 0; step < nSteps; step++) {
        const float* hcur = p ? hs1 : hs0;

        float part[4][4];
#pragma unroll
        for (int b = 0; b < 4; b++)
#pragma unroll
            for (int g = 0; g < 4; g++) part[b][g] = 0.f;

        const int k0 = ks * 32;
#pragma unroll 8
        for (int kk = 0; kk < 32; kk++) {
            const int k = k0 + kk;
            const float* w = Wsl + k * 129 + nl;
            float w0 = w[0], w1 = w[32], w2 = w[64], w3 = w[96];
#pragma unroll
            for (int b = 0; b < 4; b++) {
                float hv = hcur[b * 256 + k];
                part[b][0] += hv * w0;
                part[b][1] += hv * w1;
                part[b][2] += hv * w2;
                part[b][3] += hv * w3;
            }
        }
        {
            float* rp = red + tid * 17;
#pragma unroll
            for (int b = 0; b < 4; b++)
#pragma unroll
                for (int g = 0; g < 4; g++) rp[b * 4 + g] = part[b][g];
        }
        __syncthreads();

        float h = 0.f;
        size_t row = 0;
        if (tid < 128) {
            row = (size_t)step * 64 + bG;
            const float* xr = xg + row * 1024 + n0 + fn;
            float gi = xr[0], gf = xr[256], gg = xr[512], go = xr[768];
#pragma unroll
            for (int q = 0; q < 8; q++) {
                const float* rq = red + (q * 32 + fn) * 17 + fb * 4;
                gi += rq[0]; gf += rq[1]; gg += rq[2]; go += rq[3];
            }
            float iv = 1.f / (1.f + expf(-gi));
            float fv = 1.f / (1.f + expf(-gf));
            float gv = tanhf(gg);
            float ov = 1.f / (1.f + expf(-go));
            cS = fv * cS + iv * gv;
            h = ov * tanhf(cS);

            uint32_t hb = __float_as_uint(h);
#pragma unroll
            for (int r = 0; r < 8; r++) {
                uint32_t ra = p ? remA[r] : remB[r];
                asm volatile("st.shared::cluster.u32 [%0], %1;" :: "r"(ra), "r"(hb));
            }
        }

        asm volatile("barrier.cluster.arrive.aligned;" ::: "memory");
        if (tid < 128) {
            if (ysh) ysh[row * 256 + n0 + fn] = __float2half(h);
            if (step == nSteps - 1) {
                if (hFin) hFin[bG * 256 + n0 + fn] = h;
                if (cFin) cFin[bG * 256 + n0 + fn] = cS;
            }
        }
        asm volatile("barrier.cluster.wait.aligned;" ::: "memory");
        p ^= 1;
    }
}

// ---------------- host launch ----------------
extern "C" void kernel_launch(void* const* d_in, const int* in_sizes, int n_in,
                              void* d_out, int out_size) {
    const int*   src     = (const int*)d_in[0];
    const int*   trg     = (const int*)d_in[1];
    const float* enc_emb = (const float*)d_in[2];
    const float* dec_emb = (const float*)d_in[3];
    const float* eWih0 = (const float*)d_in[4],  *eWhh0 = (const float*)d_in[5];
    const float* ebih0 = (const float*)d_in[6],  *ebhh0 = (const float*)d_in[7];
    const float* eWih1 = (const float*)d_in[8],  *eWhh1 = (const float*)d_in[9];
    const float* ebih1 = (const float*)d_in[10], *ebhh1 = (const float*)d_in[11];
    const float* dWih0 = (const float*)d_in[12], *dWhh0 = (const float*)d_in[13];
    const float* dbih0 = (const float*)d_in[14], *dbhh0 = (const float*)d_in[15];
    const float* dWih1 = (const float*)d_in[16], *dWhh1 = (const float*)d_in[17];
    const float* dbih1 = (const float*)d_in[18], *dbhh1 = (const float*)d_in[19];
    const float* fcW   = (const float*)d_in[20], *fcb   = (const float*)d_in[21];
    float* out = (float*)d_out;

    float *pxg, *phF, *pcF;
    __half *pxh, *pyh, *pw0, *pw1, *pw2, *pw3, *pfw;
    cudaGetSymbolAddress((void**)&pxg,   g_xg);
    cudaGetSymbolAddress((void**)&phF,   g_hF);
    cudaGetSymbolAddress((void**)&pcF,   g_cF);
    cudaGetSymbolAddress((void**)&pxh,   g_xh);
    cudaGetSymbolAddress((void**)&pyh,   g_yh);
    cudaGetSymbolAddress((void**)&pw0,   g_w0);
    cudaGetSymbolAddress((void**)&pw1,   g_w1);
    cudaGetSymbolAddress((void**)&pw2,   g_w2);
    cudaGetSymbolAddress((void**)&pw3,   g_w3);
    cudaGetSymbolAddress((void**)&pfw,   g_fw);

    cudaFuncSetAttribute(lstm_rec_kernel,
                         cudaFuncAttributeMaxDynamicSharedMemorySize, REC_SMEM_BYTES);
    cudaFuncSetAttribute(gemm16_kernel,
                         cudaFuncAttributeMaxDynamicSharedMemorySize, GSMEM);

    // fused weight conversion + output-row-0 zeroing
    f2h_all_kernel<<<(8978432 / 4 + 255) / 256, 256>>>(eWih0, eWih1, dWih0, dWih1, fcW,
                                                       pw0, pw1, pw2, pw3, pfw);
    zero_first_kernel<<<(NB * NV + 255) / 256, 256>>>(out);

    // ---- Encoder ----
    embed_src_kernel<<<(NSX * NB * NE + 255) / 256, 256>>>(src, enc_emb, pxh);
    gemm16_kernel<<<dim3(4, 64), 512, GSMEM>>>(pxh, pw0, ebih0, ebhh0, pxg,
                                               G4, NE, 0);
    lstm_rec_kernel<<<128, 256, REC_SMEM_BYTES>>>(pxg, eWhh0, nullptr, nullptr,
                                                  pyh, phF, pcF, 128);
    gemm16_kernel<<<dim3(4, 64), 512, GSMEM>>>(pyh, pw1, ebih1, ebhh1, pxg,
                                               G4, NH, 0);
    lstm_rec_kernel<<<128, 256, REC_SMEM_BYTES>>>(pxg, eWhh1, nullptr, nullptr,
                                                  nullptr, phF + NB * NH, pcF + NB * NH,
                                                  128);

    // ---- Decoder (teacher forced) ----
    embed_trg_kernel<<<(127 * NB * NE + 255) / 256, 256>>>(trg, dec_emb, pxh);
    gemm16_kernel<<<dim3(4, 64), 512, GSMEM>>>(pxh, pw2, dbih0, dbhh0, pxg,
                                               G4, NE, 0);
    lstm_rec_kernel<<<128, 256, REC_SMEM_BYTES>>>(pxg, dWhh0, phF, pcF,
                                                  pyh, nullptr, nullptr, 127);
    gemm16_kernel<<<dim3(4, 64), 512, GSMEM>>>(pyh, pw3, dbih1, dbhh1, pxg,
                                               G4, NH, 0);
    lstm_rec_kernel<<<128, 256, REC_SMEM_BYTES>>>(pxg, dWhh1, phF + NB * NH, pcF + NB * NH,
                                                  pyh, nullptr, nullptr, 127);

    // ---- Output: fp16 tensor-core FC over all steps ----
    gemm16_kernel<<<dim3(125, 64), 512, GSMEM>>>(pyh, pfw, fcb, nullptr, out,
                                                 NV, NH, 1);
}

// round 9
// speedup vs baseline: 1.1390x; 1.0921x over previous
#include <cuda_runtime.h>
#include <cuda_fp16.h>
#include <cstdint>
#include <math.h>

// Problem constants
#define NB 64
#define NSX 128
#define NT 128
#define NE 128
#define NH 256
#define NV 32000
#define G4 1024

// ---------------- device scratch ----------------
__device__ float  g_xg[8192 * G4];          // x-gates fp32 (32 MB)
__device__ __half g_xh[8192 * NE];          // fp16 embedded inputs
__device__ __half g_yh[8192 * NH];          // fp16 layer outputs
__device__ float  g_hF[2 * NB * NH];
__device__ float  g_cF[2 * NB * NH];
__device__ __half g_w0[G4 * NE];            // enc Wih0 fp16
__device__ __half g_w1[G4 * NH];            // enc Wih1
__device__ __half g_w2[G4 * NE];            // dec Wih0
__device__ __half g_w3[G4 * NH];            // dec Wih1
__device__ __half g_fw[NV * NH];            // fc_W fp16

// ---------------- small helpers ----------------
__device__ __forceinline__ uint32_t smem_u32(const void* p) {
    uint32_t a;
    asm("{ .reg .u64 t; cvta.to.shared.u64 t, %1; cvt.u32.u64 %0, t; }"
        : "=r"(a) : "l"(p));
    return a;
}
__device__ __forceinline__ void cp16(uint32_t dst, const void* src) {
    asm volatile("cp.async.cg.shared.global [%0], [%1], 16;" :: "r"(dst), "l"(src));
}
__device__ __forceinline__ void ldsm4(uint32_t& r0, uint32_t& r1, uint32_t& r2,
                                      uint32_t& r3, uint32_t addr) {
    asm volatile("ldmatrix.sync.aligned.m8n8.x4.shared.b16 {%0,%1,%2,%3}, [%4];"
                 : "=r"(r0), "=r"(r1), "=r"(r2), "=r"(r3) : "r"(addr));
}
__device__ __forceinline__ void mma16816(float* c, const uint32_t* a,
                                         uint32_t b0, uint32_t b1) {
    asm volatile(
        "mma.sync.aligned.m16n8k16.row.col.f32.f16.f16.f32 "
        "{%0,%1,%2,%3}, {%4,%5,%6,%7}, {%8,%9}, {%0,%1,%2,%3};"
        : "+f"(c[0]), "+f"(c[1]), "+f"(c[2]), "+f"(c[3])
        : "r"(a[0]), "r"(a[1]), "r"(a[2]), "r"(a[3]), "r"(b0), "r"(b1));
}

// ---------------- fused conversion kernel ----------------
__global__ void f2h_all_kernel(const float* __restrict__ e0, const float* __restrict__ e1,
                               const float* __restrict__ q0, const float* __restrict__ q1,
                               const float* __restrict__ fw,
                               __half* __restrict__ w0, __half* __restrict__ w1,
                               __half* __restrict__ w2, __half* __restrict__ w3,
                               __half* __restrict__ wf) {
    int i = (blockIdx.x * blockDim.x + threadIdx.x) * 4;
    const float* s; __half* d; int off;
    if (i < 131072)      { s = e0; d = w0; off = i; }
    else if (i < 393216) { s = e1; d = w1; off = i - 131072; }
    else if (i < 524288) { s = q0; d = w2; off = i - 393216; }
    else if (i < 786432) { s = q1; d = w3; off = i - 524288; }
    else                 { s = fw; d = wf; off = i - 786432;
                           if (off >= 8192000) return; }
    float4 v = *(const float4*)(s + off);
    __half2* o = (__half2*)(d + off);
    o[0] = __floats2half2_rn(v.x, v.y);
    o[1] = __floats2half2_rn(v.z, v.w);
}

// ---------------- embedding kernels ----------------
__global__ void embed_src_kernel(const int* __restrict__ src,
                                 const float* __restrict__ emb,
                                 __half* __restrict__ out) {
    int idx = blockIdx.x * blockDim.x + threadIdx.x;
    if (idx >= NSX * NB * NE) return;
    int e = idx % NE;
    int r = idx / NE;
    int b = r % NB;
    int s = r / NB;
    out[(size_t)r * NE + e] = __float2half(emb[(size_t)src[b * NSX + s] * NE + e]);
}

__global__ void embed_trg_kernel(const int* __restrict__ trg,
                                 const float* __restrict__ emb,
                                 __half* __restrict__ out) {
    int idx = blockIdx.x * blockDim.x + threadIdx.x;
    if (idx >= 127 * NB * NE) return;
    int e = idx % NE;
    int r = idx / NE;
    int b = r % NB;
    int t = r / NB;
    int tok = (t == 0) ? 1 : trg[b * NT + t];
    out[(size_t)r * NE + e] = __float2half(emb[(size_t)tok * NE + e]);
}

__global__ void zero_first_kernel(float* __restrict__ out) {
    int idx = blockIdx.x * blockDim.x + threadIdx.x;
    if (idx >= NB * NV) return;
    int v = idx % NV;
    int b = idx / NV;
    out[(size_t)b * NT * NV + v] = 0.f;
}

// ---------------- fp16 tensor-core GEMM (2 CTAs/SM) ----------------
// Block tile 128(M) x 128(N), BK=64, 256 threads = 8 warps = 4(M)x2(N),
// warp tile 32x64. 3-stage pipeline, 32KB/stage => 96KB/CTA => 2 CTAs/SM.
// fcMode: logical row m = t*64+b -> C[(b*128 + t + 1)*NV + n], skip m >= 8128.
#define GSTAGE 32768                  // A 16KB + B 16KB
#define GSMEM  (3 * GSTAGE)

__global__ void __launch_bounds__(256, 2)
gemm16_kernel(const __half* __restrict__ A, const __half* __restrict__ W,
              const float* __restrict__ b0, const float* __restrict__ b1,
              float* __restrict__ C, int N, int K, int fcMode) {
    extern __shared__ char smbuf[];
    const uint32_t sb = smem_u32(smbuf);
    const int tid = threadIdx.x;
    const int lane = tid & 31;
    const int wid = tid >> 5;         // 0..7
    const int warp_m = wid & 3;       // 4 warps over M (32 rows each)
    const int warp_n = wid >> 2;      // 2 warps over N (64 cols each)
    const int m0 = blockIdx.y * 128;
    const int n0 = blockIdx.x * 128;
    const int KT = K >> 6;            // 2 or 4

    float acc[2][8][4];
#pragma unroll
    for (int i = 0; i < 2; i++)
#pragma unroll
        for (int j = 0; j < 8; j++)
#pragma unroll
            for (int q = 0; q < 4; q++) acc[i][j][q] = 0.f;

    auto loadStage = [&](int kt, int s) {
        const uint32_t st = sb + (uint32_t)s * GSTAGE;
        const __half* Ag = A + (size_t)m0 * K + kt * 64;
        const __half* Wg = W + (size_t)n0 * K + kt * 64;
#pragma unroll
        for (int i = 0; i < 4; i++) {            // A: 1024 16B-chunks
            int idx = i * 256 + tid;
            int row = idx >> 3, c = idx & 7;
            uint32_t off = (uint32_t)(row * 128 + ((c ^ (row & 7)) << 4));
            cp16(st + off, Ag + (size_t)row * K + c * 8);
        }
#pragma unroll
        for (int i = 0; i < 4; i++) {            // B: 1024 16B-chunks
            int idx = i * 256 + tid;
            int row = idx >> 3, c = idx & 7;
            uint32_t off = (uint32_t)(row * 128 + ((c ^ (row & 7)) << 4));
            cp16(st + 16384 + off, Wg + (size_t)row * K + c * 8);
        }
        asm volatile("cp.async.commit_group;" ::: "memory");
    };

    loadStage(0, 0);
    loadStage(1, 1);
    asm volatile("cp.async.wait_group 1;" ::: "memory");
    __syncthreads();

    for (int kt = 0; kt < KT; kt++) {
        const int s = kt % 3;
        if (kt + 2 < KT) loadStage(kt + 2, (kt + 2) % 3);
        const uint32_t stA = sb + (uint32_t)s * GSTAGE;
        const uint32_t stB = stA + 16384;
#pragma unroll
        for (int k16 = 0; k16 < 4; k16++) {
            uint32_t a[2][4];
#pragma unroll
            for (int mt = 0; mt < 2; mt++) {
                int row = warp_m * 32 + mt * 16 + (lane & 15);
                int ch = k16 * 2 + (lane >> 4);
                ldsm4(a[mt][0], a[mt][1], a[mt][2], a[mt][3],
                      stA + row * 128 + ((ch ^ (row & 7)) << 4));
            }
#pragma unroll
            for (int p = 0; p < 4; p++) {
                int nrow = warp_n * 64 + p * 16 + ((lane >> 4) & 1) * 8 + (lane & 7);
                int ch = k16 * 2 + ((lane >> 3) & 1);
                uint32_t br0, br1, br2, br3;
                ldsm4(br0, br1, br2, br3,
                      stB + nrow * 128 + ((ch ^ (nrow & 7)) << 4));
#pragma unroll
                for (int mt = 0; mt < 2; mt++) {
                    mma16816(acc[mt][2 * p],     a[mt], br0, br1);
                    mma16816(acc[mt][2 * p + 1], a[mt], br2, br3);
                }
            }
        }
        asm volatile("cp.async.wait_group 1;" ::: "memory");
        __syncthreads();
    }

    // ---- epilogue ----
    const int lrow = lane >> 2;
    const int lcol = (lane & 3) * 2;
#pragma unroll
    for (int nt = 0; nt < 8; nt++) {
        const int n = n0 + warp_n * 64 + nt * 8 + lcol;
        float bv0 = b0 ? b0[n] : 0.f;
        float bv1 = b0 ? b0[n + 1] : 0.f;
        if (b1) { bv0 += b1[n]; bv1 += b1[n + 1]; }
#pragma unroll
        for (int mt = 0; mt < 2; mt++) {
            const int mbase = m0 + warp_m * 32 + mt * 16 + lrow;
#pragma unroll
            for (int half = 0; half < 2; half++) {
                const int m = mbase + half * 8;
                float2 v;
                v.x = acc[mt][nt][half * 2 + 0] + bv0;
                v.y = acc[mt][nt][half * 2 + 1] + bv1;
                if (fcMode) {
                    if (m < 8128) {
                        int t = m >> 6, b = m & 63;
                        *(float2*)(C + ((size_t)(b * 128 + t + 1)) * NV + n) = v;
                    }
                } else {
                    *(float2*)(C + (size_t)m * N + n) = v;
                }
            }
        }
    }
}

// ---------------- clustered persistent LSTM recurrence (R6 + xg prefetch) ----------------
#define REC_SMEM_FLOATS (256 * 129 + 2 * 1024 + 8 * 32 * 17)
#define REC_SMEM_BYTES  (REC_SMEM_FLOATS * 4)

__global__ void __cluster_dims__(8, 1, 1) __launch_bounds__(256, 1)
lstm_rec_kernel(const float* __restrict__ xg,
                const float* __restrict__ Whh,
                const float* __restrict__ hInit,
                const float* __restrict__ cInit,
                __half* __restrict__ ysh,
                float* __restrict__ hFin,
                float* __restrict__ cFin,
                int nSteps) {
    extern __shared__ float smf[];
    float* Wsl = smf;                      // 256*129
    float* hs0 = Wsl + 256 * 129;          // 1024 (buffer 0)
    float* hs1 = hs0 + 1024;               // 1024 (buffer 1)
    float* red = hs1 + 1024;               // 256*17

    const int tid = threadIdx.x;
    uint32_t rank;
    asm("mov.u32 %0, %%cluster_ctarank;" : "=r"(rank));
    const int bt = blockIdx.x >> 3;
    const int n0 = (int)rank * 32;
    const int ks = tid >> 5;
    const int nl = tid & 31;

    for (int j = 0; j < 128; j++) {
        Wsl[tid * 129 + j] =
            Whh[(size_t)((j >> 5) * 256 + n0 + (j & 31)) * 256 + tid];
    }

    const int fb = tid >> 5;
    const int fn = tid & 31;
    const int bG = bt * 4 + fb;
    float cS = 0.f;
    if (tid < 128 && cInit) cS = cInit[bG * 256 + n0 + fn];

    if (hInit)
        ((float4*)hs0)[tid] = ((const float4*)(hInit + (size_t)bt * 4 * 256))[tid];
    else
        ((float4*)hs0)[tid] = make_float4(0.f, 0.f, 0.f, 0.f);

    uint32_t remA[8], remB[8];
    if (tid < 128) {
        uint32_t offs = (uint32_t)(fb * 256 + n0 + fn) * 4;
        uint32_t la = smem_u32(hs0) + offs;
        uint32_t lb = smem_u32(hs1) + offs;
#pragma unroll
        for (int r = 0; r < 8; r++) {
            asm("mapa.shared::cluster.u32 %0, %1, %2;" : "=r"(remA[r]) : "r"(la), "r"(r));
            asm("mapa.shared::cluster.u32 %0, %1, %2;" : "=r"(remB[r]) : "r"(lb), "r"(r));
        }
    }
    __syncthreads();
    asm volatile("barrier.cluster.arrive.aligned;" ::: "memory");
    asm volatile("barrier.cluster.wait.aligned;" ::: "memory");

    int p = 0;
    for (int step = 0; step < nSteps; step++) {
        // xg prefetch: issue LDGs before the matvec so L2 latency overlaps compute
        float gi = 0.f, gf = 0.f, gg = 0.f, go = 0.f;
        size_t row = 0;
        if (tid < 128) {
            row = (size_t)step * 64 + bG;
            const float* xr = xg + row * 1024 + n0 + fn;
            gi = xr[0]; gf = xr[256]; gg = xr[512]; go = xr[768];
        }

        const float* hcur = p ? hs1 : hs0;

        float part[4][4];
#pragma unroll
        for (int b = 0; b < 4; b++)
#pragma unroll
            for (int g = 0; g < 4; g++) part[b][g] = 0.f;

        const int k0 = ks * 32;
#pragma unroll 8
        for (int kk = 0; kk < 32; kk++) {
            const int k = k0 + kk;
            const float* w = Wsl + k * 129 + nl;
            float w0 = w[0], w1 = w[32], w2 = w[64], w3 = w[96];
#pragma unroll
            for (int b = 0; b < 4; b++) {
                float hv = hcur[b * 256 + k];
                part[b][0] += hv * w0;
                part[b][1] += hv * w1;
                part[b][2] += hv * w2;
                part[b][3] += hv * w3;
            }
        }
        {
            float* rp = red + tid * 17;
#pragma unroll
            for (int b = 0; b < 4; b++)
#pragma unroll
                for (int g = 0; g < 4; g++) rp[b * 4 + g] = part[b][g];
        }
        __syncthreads();

        float h = 0.f;
        if (tid < 128) {
#pragma unroll
            for (int q = 0; q < 8; q++) {
                const float* rq = red + (q * 32 + fn) * 17 + fb * 4;
                gi += rq[0]; gf += rq[1]; gg += rq[2]; go += rq[3];
            }
            float iv = 1.f / (1.f + expf(-gi));
            float fv = 1.f / (1.f + expf(-gf));
            float gv = tanhf(gg);
            float ov = 1.f / (1.f + expf(-go));
            cS = fv * cS + iv * gv;
            h = ov * tanhf(cS);

            uint32_t hb = __float_as_uint(h);
#pragma unroll
            for (int r = 0; r < 8; r++) {
                uint32_t ra = p ? remA[r] : remB[r];
                asm volatile("st.shared::cluster.u32 [%0], %1;" :: "r"(ra), "r"(hb));
            }
        }

        asm volatile("barrier.cluster.arrive.aligned;" ::: "memory");
        if (tid < 128) {
            if (ysh) ysh[row * 256 + n0 + fn] = __float2half(h);
            if (step == nSteps - 1) {
                if (hFin) hFin[bG * 256 + n0 + fn] = h;
                if (cFin) cFin[bG * 256 + n0 + fn] = cS;
            }
        }
        asm volatile("barrier.cluster.wait.aligned;" ::: "memory");
        p ^= 1;
    }
}

// ---------------- host launch ----------------
extern "C" void kernel_launch(void* const* d_in, const int* in_sizes, int n_in,
                              void* d_out, int out_size) {
    const int*   src     = (const int*)d_in[0];
    const int*   trg     = (const int*)d_in[1];
    const float* enc_emb = (const float*)d_in[2];
    const float* dec_emb = (const float*)d_in[3];
    const float* eWih0 = (const float*)d_in[4],  *eWhh0 = (const float*)d_in[5];
    const float* ebih0 = (const float*)d_in[6],  *ebhh0 = (const float*)d_in[7];
    const float* eWih1 = (const float*)d_in[8],  *eWhh1 = (const float*)d_in[9];
    const float* ebih1 = (const float*)d_in[10], *ebhh1 = (const float*)d_in[11];
    const float* dWih0 = (const float*)d_in[12], *dWhh0 = (const float*)d_in[13];
    const float* dbih0 = (const float*)d_in[14], *dbhh0 = (const float*)d_in[15];
    const float* dWih1 = (const float*)d_in[16], *dWhh1 = (const float*)d_in[17];
    const float* dbih1 = (const float*)d_in[18], *dbhh1 = (const float*)d_in[19];
    const float* fcW   = (const float*)d_in[20], *fcb   = (const float*)d_in[21];
    float* out = (float*)d_out;

    float *pxg, *phF, *pcF;
    __half *pxh, *pyh, *pw0, *pw1, *pw2, *pw3, *pfw;
    cudaGetSymbolAddress((void**)&pxg,   g_xg);
    cudaGetSymbolAddress((void**)&phF,   g_hF);
    cudaGetSymbolAddress((void**)&pcF,   g_cF);
    cudaGetSymbolAddress((void**)&pxh,   g_xh);
    cudaGetSymbolAddress((void**)&pyh,   g_yh);
    cudaGetSymbolAddress((void**)&pw0,   g_w0);
    cudaGetSymbolAddress((void**)&pw1,   g_w1);
    cudaGetSymbolAddress((void**)&pw2,   g_w2);
    cudaGetSymbolAddress((void**)&pw3,   g_w3);
    cudaGetSymbolAddress((void**)&pfw,   g_fw);

    cudaFuncSetAttribute(lstm_rec_kernel,
                         cudaFuncAttributeMaxDynamicSharedMemorySize, REC_SMEM_BYTES);
    cudaFuncSetAttribute(gemm16_kernel,
                         cudaFuncAttributeMaxDynamicSharedMemorySize, GSMEM);

    // fused weight conversion + output-row-0 zeroing
    f2h_all_kernel<<<(8978432 / 4 + 255) / 256, 256>>>(eWih0, eWih1, dWih0, dWih1, fcW,
                                                       pw0, pw1, pw2, pw3, pfw);
    zero_first_kernel<<<(NB * NV + 255) / 256, 256>>>(out);

    // ---- Encoder ----
    embed_src_kernel<<<(NSX * NB * NE + 255) / 256, 256>>>(src, enc_emb, pxh);
    gemm16_kernel<<<dim3(8, 64), 256, GSMEM>>>(pxh, pw0, ebih0, ebhh0, pxg,
                                               G4, NE, 0);
    lstm_rec_kernel<<<128, 256, REC_SMEM_BYTES>>>(pxg, eWhh0, nullptr, nullptr,
                                                  pyh, phF, pcF, 128);
    gemm16_kernel<<<dim3(8, 64), 256, GSMEM>>>(pyh, pw1, ebih1, ebhh1, pxg,
                                               G4, NH, 0);
    lstm_rec_kernel<<<128, 256, REC_SMEM_BYTES>>>(pxg, eWhh1, nullptr, nullptr,
                                                  nullptr, phF + NB * NH, pcF + NB * NH,
                                                  128);

    // ---- Decoder (teacher forced) ----
    embed_trg_kernel<<<(127 * NB * NE + 255) / 256, 256>>>(trg, dec_emb, pxh);
    gemm16_kernel<<<dim3(8, 64), 256, GSMEM>>>(pxh, pw2, dbih0, dbhh0, pxg,
                                               G4, NE, 0);
    lstm_rec_kernel<<<128, 256, REC_SMEM_BYTES>>>(pxg, dWhh0, phF, pcF,
                                                  pyh, nullptr, nullptr, 127);
    gemm16_kernel<<<dim3(8, 64), 256, GSMEM>>>(pyh, pw3, dbih1, dbhh1, pxg,
                                               G4, NH, 0);
    lstm_rec_kernel<<<128, 256, REC_SMEM_BYTES>>>(pxg, dWhh1, phF + NB * NH, pcF + NB * NH,
                                                  pyh, nullptr, nullptr, 127);

    // ---- Output: fp16 tensor-core FC over all steps ----
    gemm16_kernel<<<dim3(250, 64), 256, GSMEM>>>(pyh, pfw, fcb, nullptr, out,
                                                 NV, NH, 1);
}

// round 10
// speedup vs baseline: 1.7918x; 1.5732x over previous
#include <cuda_runtime.h>
#include <cuda_fp16.h>
#include <cstdint>
#include <math.h>

// Problem constants
#define NB 64
#define NSX 128
#define NT 128
#define NE 128
#define NH 256
#define NV 32000
#define G4 1024

// ---------------- device scratch ----------------
__device__ float  g_xg[8192 * G4];          // x-gates fp32 (32 MB)
__device__ __half g_xh[8192 * NE];          // fp16 embedded inputs
__device__ __half g_yh[8192 * NH];          // fp16 layer outputs
__device__ float  g_hF[2 * NB * NH];
__device__ float  g_cF[2 * NB * NH];
__device__ __half g_w0[G4 * NE];            // enc Wih0 fp16
__device__ __half g_w1[G4 * NH];            // enc Wih1
__device__ __half g_w2[G4 * NE];            // dec Wih0
__device__ __half g_w3[G4 * NH];            // dec Wih1
__device__ __half g_fw[NV * NH];            // fc_W fp16

// ---------------- small helpers ----------------
__device__ __forceinline__ uint32_t smem_u32(const void* p) {
    uint32_t a;
    asm("{ .reg .u64 t; cvta.to.shared.u64 t, %1; cvt.u32.u64 %0, t; }"
        : "=r"(a) : "l"(p));
    return a;
}
__device__ __forceinline__ void cp16(uint32_t dst, const void* src) {
    asm volatile("cp.async.cg.shared.global [%0], [%1], 16;" :: "r"(dst), "l"(src));
}
__device__ __forceinline__ void ldsm4(uint32_t& r0, uint32_t& r1, uint32_t& r2,
                                      uint32_t& r3, uint32_t addr) {
    asm volatile("ldmatrix.sync.aligned.m8n8.x4.shared.b16 {%0,%1,%2,%3}, [%4];"
                 : "=r"(r0), "=r"(r1), "=r"(r2), "=r"(r3) : "r"(addr));
}
__device__ __forceinline__ void mma16816(float* c, const uint32_t* a,
                                         uint32_t b0, uint32_t b1) {
    asm volatile(
        "mma.sync.aligned.m16n8k16.row.col.f32.f16.f16.f32 "
        "{%0,%1,%2,%3}, {%4,%5,%6,%7}, {%8,%9}, {%0,%1,%2,%3};"
        : "+f"(c[0]), "+f"(c[1]), "+f"(c[2]), "+f"(c[3])
        : "r"(a[0]), "r"(a[1]), "r"(a[2]), "r"(a[3]), "r"(b0), "r"(b1));
}

// ---------------- fused conversion kernel ----------------
__global__ void f2h_all_kernel(const float* __restrict__ e0, const float* __restrict__ e1,
                               const float* __restrict__ q0, const float* __restrict__ q1,
                               const float* __restrict__ fw,
                               __half* __restrict__ w0, __half* __restrict__ w1,
                               __half* __restrict__ w2, __half* __restrict__ w3,
                               __half* __restrict__ wf) {
    int i = (blockIdx.x * blockDim.x + threadIdx.x) * 4;
    const float* s; __half* d; int off;
    if (i < 131072)      { s = e0; d = w0; off = i; }
    else if (i < 393216) { s = e1; d = w1; off = i - 131072; }
    else if (i < 524288) { s = q0; d = w2; off = i - 393216; }
    else if (i < 786432) { s = q1; d = w3; off = i - 524288; }
    else                 { s = fw; d = wf; off = i - 786432;
                           if (off >= 8192000) return; }
    float4 v = *(const float4*)(s + off);
    __half2* o = (__half2*)(d + off);
    o[0] = __floats2half2_rn(v.x, v.y);
    o[1] = __floats2half2_rn(v.z, v.w);
}

// ---------------- embedding kernels ----------------
__global__ void embed_src_kernel(const int* __restrict__ src,
                                 const float* __restrict__ emb,
                                 __half* __restrict__ out) {
    int idx = blockIdx.x * blockDim.x + threadIdx.x;
    if (idx >= NSX * NB * NE) return;
    int e = idx % NE;
    int r = idx / NE;
    int b = r % NB;
    int s = r / NB;
    out[(size_t)r * NE + e] = __float2half(emb[(size_t)src[b * NSX + s] * NE + e]);
}

__global__ void embed_trg_kernel(const int* __restrict__ trg,
                                 const float* __restrict__ emb,
                                 __half* __restrict__ out) {
    int idx = blockIdx.x * blockDim.x + threadIdx.x;
    if (idx >= 127 * NB * NE) return;
    int e = idx % NE;
    int r = idx / NE;
    int b = r % NB;
    int t = r / NB;
    int tok = (t == 0) ? 1 : trg[b * NT + t];
    out[(size_t)r * NE + e] = __float2half(emb[(size_t)tok * NE + e]);
}

__global__ void zero_first_kernel(float* __restrict__ out) {
    int idx = blockIdx.x * blockDim.x + threadIdx.x;
    if (idx >= NB * NV) return;
    int v = idx % NV;
    int b = idx / NV;
    out[(size_t)b * NT * NV + v] = 0.f;
}

// ---------------- fp16 tensor-core GEMM (2 CTAs/SM) ----------------
// Block tile 128(M) x 128(N), BK=64, 256 threads = 8 warps = 4(M)x2(N).
#define GSTAGE 32768
#define GSMEM  (3 * GSTAGE)

__global__ void __launch_bounds__(256, 2)
gemm16_kernel(const __half* __restrict__ A, const __half* __restrict__ W,
              const float* __restrict__ b0, const float* __restrict__ b1,
              float* __restrict__ C, int N, int K, int fcMode) {
    extern __shared__ char smbuf[];
    const uint32_t sb = smem_u32(smbuf);
    const int tid = threadIdx.x;
    const int lane = tid & 31;
    const int wid = tid >> 5;
    const int warp_m = wid & 3;
    const int warp_n = wid >> 2;
    const int m0 = blockIdx.y * 128;
    const int n0 = blockIdx.x * 128;
    const int KT = K >> 6;

    float acc[2][8][4];
#pragma unroll
    for (int i = 0; i < 2; i++)
#pragma unroll
        for (int j = 0; j < 8; j++)
#pragma unroll
            for (int q = 0; q < 4; q++) acc[i][j][q] = 0.f;

    auto loadStage = [&](int kt, int s) {
        const uint32_t st = sb + (uint32_t)s * GSTAGE;
        const __half* Ag = A + (size_t)m0 * K + kt * 64;
        const __half* Wg = W + (size_t)n0 * K + kt * 64;
#pragma unroll
        for (int i = 0; i < 4; i++) {
            int idx = i * 256 + tid;
            int row = idx >> 3, c = idx & 7;
            uint32_t off = (uint32_t)(row * 128 + ((c ^ (row & 7)) << 4));
            cp16(st + off, Ag + (size_t)row * K + c * 8);
        }
#pragma unroll
        for (int i = 0; i < 4; i++) {
            int idx = i * 256 + tid;
            int row = idx >> 3, c = idx & 7;
            uint32_t off = (uint32_t)(row * 128 + ((c ^ (row & 7)) << 4));
            cp16(st + 16384 + off, Wg + (size_t)row * K + c * 8);
        }
        asm volatile("cp.async.commit_group;" ::: "memory");
    };

    loadStage(0, 0);
    loadStage(1, 1);
    asm volatile("cp.async.wait_group 1;" ::: "memory");
    __syncthreads();

    for (int kt = 0; kt < KT; kt++) {
        const int s = kt % 3;
        if (kt + 2 < KT) loadStage(kt + 2, (kt + 2) % 3);
        const uint32_t stA = sb + (uint32_t)s * GSTAGE;
        const uint32_t stB = stA + 16384;
#pragma unroll
        for (int k16 = 0; k16 < 4; k16++) {
            uint32_t a[2][4];
#pragma unroll
            for (int mt = 0; mt < 2; mt++) {
                int row = warp_m * 32 + mt * 16 + (lane & 15);
                int ch = k16 * 2 + (lane >> 4);
                ldsm4(a[mt][0], a[mt][1], a[mt][2], a[mt][3],
                      stA + row * 128 + ((ch ^ (row & 7)) << 4));
            }
#pragma unroll
            for (int p = 0; p < 4; p++) {
                int nrow = warp_n * 64 + p * 16 + ((lane >> 4) & 1) * 8 + (lane & 7);
                int ch = k16 * 2 + ((lane >> 3) & 1);
                uint32_t br0, br1, br2, br3;
                ldsm4(br0, br1, br2, br3,
                      stB + nrow * 128 + ((ch ^ (nrow & 7)) << 4));
#pragma unroll
                for (int mt = 0; mt < 2; mt++) {
                    mma16816(acc[mt][2 * p],     a[mt], br0, br1);
                    mma16816(acc[mt][2 * p + 1], a[mt], br2, br3);
                }
            }
        }
        asm volatile("cp.async.wait_group 1;" ::: "memory");
        __syncthreads();
    }

    const int lrow = lane >> 2;
    const int lcol = (lane & 3) * 2;
#pragma unroll
    for (int nt = 0; nt < 8; nt++) {
        const int n = n0 + warp_n * 64 + nt * 8 + lcol;
        float bv0 = b0 ? b0[n] : 0.f;
        float bv1 = b0 ? b0[n + 1] : 0.f;
        if (b1) { bv0 += b1[n]; bv1 += b1[n + 1]; }
#pragma unroll
        for (int mt = 0; mt < 2; mt++) {
            const int mbase = m0 + warp_m * 32 + mt * 16 + lrow;
#pragma unroll
            for (int half = 0; half < 2; half++) {
                const int m = mbase + half * 8;
                float2 v;
                v.x = acc[mt][nt][half * 2 + 0] + bv0;
                v.y = acc[mt][nt][half * 2 + 1] + bv1;
                if (fcMode) {
                    if (m < 8128) {
                        int t = m >> 6, b = m & 63;
                        *(float2*)(C + ((size_t)(b * 128 + t + 1)) * NV + n) = v;
                    }
                } else {
                    *(float2*)(C + (size_t)m * N + n) = v;
                }
            }
        }
    }
}

// ---------------- clustered HMMA LSTM recurrence ----------------
// 16 clusters x 8 CTAs; cluster owns 4 batches; CTA owns 128 gate cols
// (32 per gate block) with FULL K=256 -> no cross-CTA reduction.
// Whh slice as fp16 in smem (swizzled, 512B rows); h broadcast as fp16 via
// DSMEM into double-buffered [16][256] fp16 tiles (rows 4-15 zero padding).
// Matvec = 16x ldsm4(A) + 16x ldsm4(B) + 32x HMMA per warp per step.
#define RECSM_W   0
#define RECSM_H0  65536
#define RECSM_H1  (65536 + 8192)
#define RECSM_SG  (65536 + 16384)
#define REC_SMEM_BYTES (65536 + 16384 + 2048)

__global__ void __cluster_dims__(8, 1, 1) __launch_bounds__(256, 1)
lstm_rec_kernel(const float* __restrict__ xg,
                const float* __restrict__ Whh,
                const float* __restrict__ hInit,
                const float* __restrict__ cInit,
                __half* __restrict__ ysh,
                float* __restrict__ hFin,
                float* __restrict__ cFin,
                int nSteps) {
    extern __shared__ char smb[];
    const uint32_t sb = smem_u32(smb);
    float* sg = (float*)(smb + RECSM_SG);      // [4 gates][4 batch][32 cols]

    const int tid = threadIdx.x;
    const int lane = tid & 31;
    const int wid = tid >> 5;
    uint32_t rank;
    asm("mov.u32 %0, %%cluster_ctarank;" : "=r"(rank));
    const int bt = blockIdx.x >> 3;            // cluster id
    const int n0 = (int)rank * 32;

    // zero both h buffers (16 KB)
    for (int i = tid; i < 4096; i += 256)
        ((uint32_t*)(smb + RECSM_H0))[i] = 0u;

    // fill Whh slice -> fp16 swizzled smem. local row r (0..127):
    // global row = (r>>5)*256 + n0 + (r&31); 512B rows, chunk = k/8 ^ (r&7)
#pragma unroll 4
    for (int it = 0; it < 32; it++) {
        int idx = it * 256 + tid;              // 8192 float4 chunks
        int r = idx >> 6, c4 = idx & 63;
        int grow = (r >> 5) * 256 + n0 + (r & 31);
        float4 v = *(const float4*)(Whh + (size_t)grow * 256 + c4 * 4);
        int k = c4 * 4;
        int chunk = (k >> 3) ^ (r & 7);
        __half2* d = (__half2*)(smb + RECSM_W + r * 512 + chunk * 16 + (k & 7) * 2);
        d[0] = __floats2half2_rn(v.x, v.y);
        d[1] = __floats2half2_rn(v.z, v.w);
    }
    __syncthreads();

    // init h buffer 0 rows 0-3 (fp32 -> fp16, swizzled)
    if (hInit) {
        int b = tid >> 6, k = (tid & 63) * 4;
        float4 v = *(const float4*)(hInit + (size_t)(bt * 4 + b) * 256 + k);
        int chunk = (k >> 3) ^ b;
        __half2* d = (__half2*)(smb + RECSM_H0 + b * 512 + chunk * 16 + (k & 7) * 2);
        d[0] = __floats2half2_rn(v.x, v.y);
        d[1] = __floats2half2_rn(v.z, v.w);
    }

    const int fb = tid >> 5;                   // finalize threads (tid<128)
    const int fn = tid & 31;
    const int bG = bt * 4 + fb;
    float cS = 0.f;
    if (tid < 128 && cInit) cS = cInit[bG * 256 + n0 + fn];

    // remote DSMEM addrs for this thread's h element (batch fb, hidden n0+fn)
    uint32_t remA[8], remB[8];
    if (tid < 128) {
        int kg = n0 + fn;
        uint32_t off = (uint32_t)(fb * 512 + (((kg >> 3) ^ fb) << 4) + (kg & 7) * 2);
        uint32_t la = sb + RECSM_H0 + off;
        uint32_t lb = sb + RECSM_H1 + off;
#pragma unroll
        for (int r = 0; r < 8; r++) {
            asm("mapa.shared::cluster.u32 %0, %1, %2;" : "=r"(remA[r]) : "r"(la), "r"(r));
            asm("mapa.shared::cluster.u32 %0, %1, %2;" : "=r"(remB[r]) : "r"(lb), "r"(r));
        }
    }
    __syncthreads();
    asm volatile("barrier.cluster.arrive.aligned;" ::: "memory");
    asm volatile("barrier.cluster.wait.aligned;" ::: "memory");

    // B-frag addressing (step-invariant)
    const int nrow = wid * 16 + ((lane >> 4) & 1) * 8 + (lane & 7);
    const uint32_t bAddrBase = sb + RECSM_W + nrow * 512;
    const int brow7 = nrow & 7;
    const int arow = lane & 15;
    const int asel = lane >> 4;

    int p = 0;
    for (int step = 0; step < nSteps; step++) {
        // xg prefetch (L2 latency overlaps matvec)
        float gi = 0.f, gf = 0.f, gg = 0.f, go = 0.f;
        size_t row = 0;
        if (tid < 128) {
            row = (size_t)step * 64 + bG;
            const float* xr = xg + row * 1024 + n0 + fn;
            gi = xr[0]; gf = xr[256]; gg = xr[512]; go = xr[768];
        }

        const uint32_t hbase = sb + (p ? RECSM_H1 : RECSM_H0) + arow * 512;
        const int arow7 = arow & 7;

        float acc0[4] = {0.f, 0.f, 0.f, 0.f};
        float acc1[4] = {0.f, 0.f, 0.f, 0.f};
#pragma unroll
        for (int kk = 0; kk < 16; kk++) {
            uint32_t a[4];
            ldsm4(a[0], a[1], a[2], a[3],
                  hbase + (uint32_t)(((kk * 2 + asel) ^ arow7) << 4));
            uint32_t b0, b1, b2, b3;
            ldsm4(b0, b1, b2, b3,
                  bAddrBase + (uint32_t)(((kk * 2 + ((lane >> 3) & 1)) ^ brow7) << 4));
            mma16816(acc0, a, b0, b1);
            mma16816(acc1, a, b2, b3);
        }

        // exchange: rows 0-3 (real batches) live in lanes 0-15 (c0,c1)
        if (lane < 16) {
            int g = wid >> 1, b = lane >> 2;
            int jb = (wid & 1) * 16 + (lane & 3) * 2;
            *(float2*)&sg[(g * 4 + b) * 32 + jb] = make_float2(acc0[0], acc0[1]);
            *(float2*)&sg[(g * 4 + b) * 32 + jb + 8] = make_float2(acc1[0], acc1[1]);
        }
        __syncthreads();

        float h = 0.f;
        if (tid < 128) {
            gi += sg[(0 * 4 + fb) * 32 + fn];
            gf += sg[(1 * 4 + fb) * 32 + fn];
            gg += sg[(2 * 4 + fb) * 32 + fn];
            go += sg[(3 * 4 + fb) * 32 + fn];
            float iv = 1.f / (1.f + expf(-gi));
            float fv = 1.f / (1.f + expf(-gf));
            float gv = tanhf(gg);
            float ov = 1.f / (1.f + expf(-go));
            cS = fv * cS + iv * gv;
            h = ov * tanhf(cS);

            unsigned short hu = __half_as_ushort(__float2half(h));
#pragma unroll
            for (int r = 0; r < 8; r++) {
                uint32_t ra = p ? remA[r] : remB[r];   // write buffer p^1
                asm volatile("st.shared::cluster.u16 [%0], %1;" :: "r"(ra), "h"(hu) : "memory");
            }
        }

        asm volatile("barrier.cluster.arrive.aligned;" ::: "memory");
        if (tid < 128) {
            if (ysh) ysh[row * 256 + n0 + fn] = __float2half(h);
            if (step == nSteps - 1) {
                if (hFin) hFin[bG * 256 + n0 + fn] = h;
                if (cFin) cFin[bG * 256 + n0 + fn] = cS;
            }
        }
        asm volatile("barrier.cluster.wait.aligned;" ::: "memory");
        __syncthreads();
        p ^= 1;
    }
}

// ---------------- host launch ----------------
extern "C" void kernel_launch(void* const* d_in, const int* in_sizes, int n_in,
                              void* d_out, int out_size) {
    const int*   src     = (const int*)d_in[0];
    const int*   trg     = (const int*)d_in[1];
    const float* enc_emb = (const float*)d_in[2];
    const float* dec_emb = (const float*)d_in[3];
    const float* eWih0 = (const float*)d_in[4],  *eWhh0 = (const float*)d_in[5];
    const float* ebih0 = (const float*)d_in[6],  *ebhh0 = (const float*)d_in[7];
    const float* eWih1 = (const float*)d_in[8],  *eWhh1 = (const float*)d_in[9];
    const float* ebih1 = (const float*)d_in[10], *ebhh1 = (const float*)d_in[11];
    const float* dWih0 = (const float*)d_in[12], *dWhh0 = (const float*)d_in[13];
    const float* dbih0 = (const float*)d_in[14], *dbhh0 = (const float*)d_in[15];
    const float* dWih1 = (const float*)d_in[16], *dWhh1 = (const float*)d_in[17];
    const float* dbih1 = (const float*)d_in[18], *dbhh1 = (const float*)d_in[19];
    const float* fcW   = (const float*)d_in[20], *fcb   = (const float*)d_in[21];
    float* out = (float*)d_out;

    float *pxg, *phF, *pcF;
    __half *pxh, *pyh, *pw0, *pw1, *pw2, *pw3, *pfw;
    cudaGetSymbolAddress((void**)&pxg,   g_xg);
    cudaGetSymbolAddress((void**)&phF,   g_hF);
    cudaGetSymbolAddress((void**)&pcF,   g_cF);
    cudaGetSymbolAddress((void**)&pxh,   g_xh);
    cudaGetSymbolAddress((void**)&pyh,   g_yh);
    cudaGetSymbolAddress((void**)&pw0,   g_w0);
    cudaGetSymbolAddress((void**)&pw1,   g_w1);
    cudaGetSymbolAddress((void**)&pw2,   g_w2);
    cudaGetSymbolAddress((void**)&pw3,   g_w3);
    cudaGetSymbolAddress((void**)&pfw,   g_fw);

    cudaFuncSetAttribute(lstm_rec_kernel,
                         cudaFuncAttributeMaxDynamicSharedMemorySize, REC_SMEM_BYTES);
    cudaFuncSetAttribute(gemm16_kernel,
                         cudaFuncAttributeMaxDynamicSharedMemorySize, GSMEM);

    // fused weight conversion + output-row-0 zeroing
    f2h_all_kernel<<<(8978432 / 4 + 255) / 256, 256>>>(eWih0, eWih1, dWih0, dWih1, fcW,
                                                       pw0, pw1, pw2, pw3, pfw);
    zero_first_kernel<<<(NB * NV + 255) / 256, 256>>>(out);

    // ---- Encoder ----
    embed_src_kernel<<<(NSX * NB * NE + 255) / 256, 256>>>(src, enc_emb, pxh);
    gemm16_kernel<<<dim3(8, 64), 256, GSMEM>>>(pxh, pw0, ebih0, ebhh0, pxg,
                                               G4, NE, 0);
    lstm_rec_kernel<<<128, 256, REC_SMEM_BYTES>>>(pxg, eWhh0, nullptr, nullptr,
                                                  pyh, phF, pcF, 128);
    gemm16_kernel<<<dim3(8, 64), 256, GSMEM>>>(pyh, pw1, ebih1, ebhh1, pxg,
                                               G4, NH, 0);
    lstm_rec_kernel<<<128, 256, REC_SMEM_BYTES>>>(pxg, eWhh1, nullptr, nullptr,
                                                  nullptr, phF + NB * NH, pcF + NB * NH,
                                                  128);

    // ---- Decoder (teacher forced) ----
    embed_trg_kernel<<<(127 * NB * NE + 255) / 256, 256>>>(trg, dec_emb, pxh);
    gemm16_kernel<<<dim3(8, 64), 256, GSMEM>>>(pxh, pw2, dbih0, dbhh0, pxg,
                                               G4, NE, 0);
    lstm_rec_kernel<<<128, 256, REC_SMEM_BYTES>>>(pxg, dWhh0, phF, pcF,
                                                  pyh, nullptr, nullptr, 127);
    gemm16_kernel<<<dim3(8, 64), 256, GSMEM>>>(pyh, pw3, dbih1, dbhh1, pxg,
                                               G4, NH, 0);
    lstm_rec_kernel<<<128, 256, REC_SMEM_BYTES>>>(pxg, dWhh1, phF + NB * NH, pcF + NB * NH,
                                                  pyh, nullptr, nullptr, 127);

    // ---- Output: fp16 tensor-core FC over all steps ----
    gemm16_kernel<<<dim3(250, 64), 256, GSMEM>>>(pyh, pfw, fcb, nullptr, out,
                                                 NV, NH, 1);
}

// round 11
// speedup vs baseline: 1.8359x; 1.0246x over previous
#include <cuda_runtime.h>
#include <cuda_fp16.h>
#include <cstdint>
#include <math.h>

// Problem constants
#define NB 64
#define NSX 128
#define NT 128
#define NE 128
#define NH 256
#define NV 32000
#define G4 1024

// ---------------- device scratch ----------------
__device__ float  g_xg[8192 * G4];          // x-gates fp32 (32 MB)
__device__ __half g_xh[8192 * NE];          // fp16 embedded inputs
__device__ __half g_yh[8192 * NH];          // fp16 layer outputs
__device__ float  g_hF[2 * NB * NH];
__device__ float  g_cF[2 * NB * NH];
__device__ __half g_w0[G4 * NE];            // enc Wih0 fp16
__device__ __half g_w1[G4 * NH];            // enc Wih1
__device__ __half g_w2[G4 * NE];            // dec Wih0
__device__ __half g_w3[G4 * NH];            // dec Wih1
__device__ __half g_fw[NV * NH];            // fc_W fp16

// ---------------- small helpers ----------------
__device__ __forceinline__ uint32_t smem_u32(const void* p) {
    uint32_t a;
    asm("{ .reg .u64 t; cvta.to.shared.u64 t, %1; cvt.u32.u64 %0, t; }"
        : "=r"(a) : "l"(p));
    return a;
}
__device__ __forceinline__ void cp16(uint32_t dst, const void* src) {
    asm volatile("cp.async.cg.shared.global [%0], [%1], 16;" :: "r"(dst), "l"(src));
}
__device__ __forceinline__ void ldsm4(uint32_t& r0, uint32_t& r1, uint32_t& r2,
                                      uint32_t& r3, uint32_t addr) {
    asm volatile("ldmatrix.sync.aligned.m8n8.x4.shared.b16 {%0,%1,%2,%3}, [%4];"
                 : "=r"(r0), "=r"(r1), "=r"(r2), "=r"(r3) : "r"(addr));
}
__device__ __forceinline__ void mma16816(float* c, const uint32_t* a,
                                         uint32_t b0, uint32_t b1) {
    asm volatile(
        "mma.sync.aligned.m16n8k16.row.col.f32.f16.f16.f32 "
        "{%0,%1,%2,%3}, {%4,%5,%6,%7}, {%8,%9}, {%0,%1,%2,%3};"
        : "+f"(c[0]), "+f"(c[1]), "+f"(c[2]), "+f"(c[3])
        : "r"(a[0]), "r"(a[1]), "r"(a[2]), "r"(a[3]), "r"(b0), "r"(b1));
}

// ---------------- fused conversion kernel ----------------
__global__ void f2h_all_kernel(const float* __restrict__ e0, const float* __restrict__ e1,
                               const float* __restrict__ q0, const float* __restrict__ q1,
                               const float* __restrict__ fw,
                               __half* __restrict__ w0, __half* __restrict__ w1,
                               __half* __restrict__ w2, __half* __restrict__ w3,
                               __half* __restrict__ wf) {
    int i = (blockIdx.x * blockDim.x + threadIdx.x) * 4;
    const float* s; __half* d; int off;
    if (i < 131072)      { s = e0; d = w0; off = i; }
    else if (i < 393216) { s = e1; d = w1; off = i - 131072; }
    else if (i < 524288) { s = q0; d = w2; off = i - 393216; }
    else if (i < 786432) { s = q1; d = w3; off = i - 524288; }
    else                 { s = fw; d = wf; off = i - 786432;
                           if (off >= 8192000) return; }
    float4 v = *(const float4*)(s + off);
    __half2* o = (__half2*)(d + off);
    o[0] = __floats2half2_rn(v.x, v.y);
    o[1] = __floats2half2_rn(v.z, v.w);
}

// ---------------- embedding kernels ----------------
__global__ void embed_src_kernel(const int* __restrict__ src,
                                 const float* __restrict__ emb,
                                 __half* __restrict__ out) {
    int idx = blockIdx.x * blockDim.x + threadIdx.x;
    if (idx >= NSX * NB * NE) return;
    int e = idx % NE;
    int r = idx / NE;
    int b = r % NB;
    int s = r / NB;
    out[(size_t)r * NE + e] = __float2half(emb[(size_t)src[b * NSX + s] * NE + e]);
}

__global__ void embed_trg_kernel(const int* __restrict__ trg,
                                 const float* __restrict__ emb,
                                 __half* __restrict__ out) {
    int idx = blockIdx.x * blockDim.x + threadIdx.x;
    if (idx >= 127 * NB * NE) return;
    int e = idx % NE;
    int r = idx / NE;
    int b = r % NB;
    int t = r / NB;
    int tok = (t == 0) ? 1 : trg[b * NT + t];
    out[(size_t)r * NE + e] = __float2half(emb[(size_t)tok * NE + e]);
}

__global__ void zero_first_kernel(float* __restrict__ out) {
    int idx = blockIdx.x * blockDim.x + threadIdx.x;
    if (idx >= NB * NV) return;
    int v = idx % NV;
    int b = idx / NV;
    out[(size_t)b * NT * NV + v] = 0.f;
}

// ---------------- fp16 tensor-core GEMM (3 CTAs/SM, low-reg) ----------------
// Block tile 128(M) x 64(N), BK=64, 256 threads = 8 warps = 4(M)x2(N),
// warp tile 32x32 (~70 regs). 3-stage pipeline 24KB/stage => 72KB/CTA =>
// 3 CTAs/SM (24 warps = 6/SMSP) for latency hiding.
// fcMode: logical row m = t*64+b -> C[(b*128 + t + 1)*NV + n], skip m >= 8128.
#define GSTAGE 24576                  // A 16KB + B 8KB
#define GSMEM  (3 * GSTAGE)

__global__ void __launch_bounds__(256, 3)
gemm16_kernel(const __half* __restrict__ A, const __half* __restrict__ W,
              const float* __restrict__ b0, const float* __restrict__ b1,
              float* __restrict__ C, int N, int K, int fcMode) {
    extern __shared__ char smbuf[];
    const uint32_t sb = smem_u32(smbuf);
    const int tid = threadIdx.x;
    const int lane = tid & 31;
    const int wid = tid >> 5;
    const int warp_m = wid & 3;       // 4 warps over M (32 rows each)
    const int warp_n = wid >> 2;      // 2 warps over N (32 cols each)
    const int m0 = blockIdx.y * 128;
    const int n0 = blockIdx.x * 64;
    const int KT = K >> 6;            // 2 or 4

    float acc[2][4][4];
#pragma unroll
    for (int i = 0; i < 2; i++)
#pragma unroll
        for (int j = 0; j < 4; j++)
#pragma unroll
            for (int q = 0; q < 4; q++) acc[i][j][q] = 0.f;

    auto loadStage = [&](int kt, int s) {
        const uint32_t st = sb + (uint32_t)s * GSTAGE;
        const __half* Ag = A + (size_t)m0 * K + kt * 64;
        const __half* Wg = W + (size_t)n0 * K + kt * 64;
#pragma unroll
        for (int i = 0; i < 4; i++) {            // A: 1024 16B-chunks
            int idx = i * 256 + tid;
            int row = idx >> 3, c = idx & 7;
            uint32_t off = (uint32_t)(row * 128 + ((c ^ (row & 7)) << 4));
            cp16(st + off, Ag + (size_t)row * K + c * 8);
        }
#pragma unroll
        for (int i = 0; i < 2; i++) {            // B: 512 16B-chunks
            int idx = i * 256 + tid;
            int row = idx >> 3, c = idx & 7;
            uint32_t off = (uint32_t)(row * 128 + ((c ^ (row & 7)) << 4));
            cp16(st + 16384 + off, Wg + (size_t)row * K + c * 8);
        }
        asm volatile("cp.async.commit_group;" ::: "memory");
    };

    loadStage(0, 0);
    loadStage(1, 1);
    asm volatile("cp.async.wait_group 1;" ::: "memory");
    __syncthreads();

    for (int kt = 0; kt < KT; kt++) {
        const int s = kt % 3;
        if (kt + 2 < KT) loadStage(kt + 2, (kt + 2) % 3);
        const uint32_t stA = sb + (uint32_t)s * GSTAGE;
        const uint32_t stB = stA + 16384;
#pragma unroll
        for (int k16 = 0; k16 < 4; k16++) {
            uint32_t a[2][4];
#pragma unroll
            for (int mt = 0; mt < 2; mt++) {
                int row = warp_m * 32 + mt * 16 + (lane & 15);
                int ch = k16 * 2 + (lane >> 4);
                ldsm4(a[mt][0], a[mt][1], a[mt][2], a[mt][3],
                      stA + row * 128 + ((ch ^ (row & 7)) << 4));
            }
#pragma unroll
            for (int p = 0; p < 2; p++) {
                int nrow = warp_n * 32 + p * 16 + ((lane >> 4) & 1) * 8 + (lane & 7);
                int ch = k16 * 2 + ((lane >> 3) & 1);
                uint32_t br0, br1, br2, br3;
                ldsm4(br0, br1, br2, br3,
                      stB + nrow * 128 + ((ch ^ (nrow & 7)) << 4));
#pragma unroll
                for (int mt = 0; mt < 2; mt++) {
                    mma16816(acc[mt][2 * p],     a[mt], br0, br1);
                    mma16816(acc[mt][2 * p + 1], a[mt], br2, br3);
                }
            }
        }
        asm volatile("cp.async.wait_group 1;" ::: "memory");
        __syncthreads();
    }

    // ---- epilogue ----
    const int lrow = lane >> 2;
    const int lcol = (lane & 3) * 2;
#pragma unroll
    for (int nt = 0; nt < 4; nt++) {
        const int n = n0 + warp_n * 32 + nt * 8 + lcol;
        float bv0 = b0 ? b0[n] : 0.f;
        float bv1 = b0 ? b0[n + 1] : 0.f;
        if (b1) { bv0 += b1[n]; bv1 += b1[n + 1]; }
#pragma unroll
        for (int mt = 0; mt < 2; mt++) {
            const int mbase = m0 + warp_m * 32 + mt * 16 + lrow;
#pragma unroll
            for (int half = 0; half < 2; half++) {
                const int m = mbase + half * 8;
                float2 v;
                v.x = acc[mt][nt][half * 2 + 0] + bv0;
                v.y = acc[mt][nt][half * 2 + 1] + bv1;
                if (fcMode) {
                    if (m < 8128) {
                        int t = m >> 6, b = m & 63;
                        *(float2*)(C + ((size_t)(b * 128 + t + 1)) * NV + n) = v;
                    }
                } else {
                    *(float2*)(C + (size_t)m * N + n) = v;
                }
            }
        }
    }
}

// ---------------- clustered HMMA LSTM recurrence ----------------
// 16 clusters x 8 CTAs; cluster owns 4 batches; CTA owns 128 gate cols
// (32 per gate block) with FULL K=256 -> no cross-CTA reduction.
#define RECSM_W   0
#define RECSM_H0  65536
#define RECSM_H1  (65536 + 8192)
#define RECSM_SG  (65536 + 16384)
#define REC_SMEM_BYTES (65536 + 16384 + 2048)

__global__ void __cluster_dims__(8, 1, 1) __launch_bounds__(256, 1)
lstm_rec_kernel(const float* __restrict__ xg,
                const float* __restrict__ Whh,
                const float* __restrict__ hInit,
                const float* __restrict__ cInit,
                __half* __restrict__ ysh,
                float* __restrict__ hFin,
                float* __restrict__ cFin,
                int nSteps) {
    extern __shared__ char smb[];
    const uint32_t sb = smem_u32(smb);
    float* sg = (float*)(smb + RECSM_SG);      // [4 gates][4 batch][32 cols]

    const int tid = threadIdx.x;
    const int lane = tid & 31;
    const int wid = tid >> 5;
    uint32_t rank;
    asm("mov.u32 %0, %%cluster_ctarank;" : "=r"(rank));
    const int bt = blockIdx.x >> 3;            // cluster id
    const int n0 = (int)rank * 32;

    // zero both h buffers (16 KB)
    for (int i = tid; i < 4096; i += 256)
        ((uint32_t*)(smb + RECSM_H0))[i] = 0u;

    // fill Whh slice -> fp16 swizzled smem
#pragma unroll 4
    for (int it = 0; it < 32; it++) {
        int idx = it * 256 + tid;              // 8192 float4 chunks
        int r = idx >> 6, c4 = idx & 63;
        int grow = (r >> 5) * 256 + n0 + (r & 31);
        float4 v = *(const float4*)(Whh + (size_t)grow * 256 + c4 * 4);
        int k = c4 * 4;
        int chunk = (k >> 3) ^ (r & 7);
        __half2* d = (__half2*)(smb + RECSM_W + r * 512 + chunk * 16 + (k & 7) * 2);
        d[0] = __floats2half2_rn(v.x, v.y);
        d[1] = __floats2half2_rn(v.z, v.w);
    }
    __syncthreads();

    // init h buffer 0 rows 0-3 (fp32 -> fp16, swizzled)
    if (hInit) {
        int b = tid >> 6, k = (tid & 63) * 4;
        float4 v = *(const float4*)(hInit + (size_t)(bt * 4 + b) * 256 + k);
        int chunk = (k >> 3) ^ b;
        __half2* d = (__half2*)(smb + RECSM_H0 + b * 512 + chunk * 16 + (k & 7) * 2);
        d[0] = __floats2half2_rn(v.x, v.y);
        d[1] = __floats2half2_rn(v.z, v.w);
    }

    const int fb = tid >> 5;                   // finalize threads (tid<128)
    const int fn = tid & 31;
    const int bG = bt * 4 + fb;
    float cS = 0.f;
    if (tid < 128 && cInit) cS = cInit[bG * 256 + n0 + fn];

    // remote DSMEM addrs for this thread's h element
    uint32_t remA[8], remB[8];
    if (tid < 128) {
        int kg = n0 + fn;
        uint32_t off = (uint32_t)(fb * 512 + (((kg >> 3) ^ fb) << 4) + (kg & 7) * 2);
        uint32_t la = sb + RECSM_H0 + off;
        uint32_t lb = sb + RECSM_H1 + off;
#pragma unroll
        for (int r = 0; r < 8; r++) {
            asm("mapa.shared::cluster.u32 %0, %1, %2;" : "=r"(remA[r]) : "r"(la), "r"(r));
            asm("mapa.shared::cluster.u32 %0, %1, %2;" : "=r"(remB[r]) : "r"(lb), "r"(r));
        }
    }
    __syncthreads();
    asm volatile("barrier.cluster.arrive.aligned;" ::: "memory");
    asm volatile("barrier.cluster.wait.aligned;" ::: "memory");

    // B-frag addressing (step-invariant)
    const int nrow = wid * 16 + ((lane >> 4) & 1) * 8 + (lane & 7);
    const uint32_t bAddrBase = sb + RECSM_W + nrow * 512;
    const int brow7 = nrow & 7;
    const int arow = lane & 15;
    const int asel = lane >> 4;

    int p = 0;
    for (int step = 0; step < nSteps; step++) {
        // xg prefetch (L2 latency overlaps matvec)
        float gi = 0.f, gf = 0.f, gg = 0.f, go = 0.f;
        size_t row = 0;
        if (tid < 128) {
            row = (size_t)step * 64 + bG;
            const float* xr = xg + row * 1024 + n0 + fn;
            gi = xr[0]; gf = xr[256]; gg = xr[512]; go = xr[768];
        }

        const uint32_t hbase = sb + (p ? RECSM_H1 : RECSM_H0) + arow * 512;
        const int arow7 = arow & 7;

        float acc0[4] = {0.f, 0.f, 0.f, 0.f};
        float acc1[4] = {0.f, 0.f, 0.f, 0.f};
#pragma unroll
        for (int kk = 0; kk < 16; kk++) {
            uint32_t a[4];
            ldsm4(a[0], a[1], a[2], a[3],
                  hbase + (uint32_t)(((kk * 2 + asel) ^ arow7) << 4));
            uint32_t b0, b1, b2, b3;
            ldsm4(b0, b1, b2, b3,
                  bAddrBase + (uint32_t)(((kk * 2 + ((lane >> 3) & 1)) ^ brow7) << 4));
            mma16816(acc0, a, b0, b1);
            mma16816(acc1, a, b2, b3);
        }

        // exchange: rows 0-3 (real batches) live in lanes 0-15 (c0,c1)
        if (lane < 16) {
            int g = wid >> 1, b = lane >> 2;
            int jb = (wid & 1) * 16 + (lane & 3) * 2;
            *(float2*)&sg[(g * 4 + b) * 32 + jb] = make_float2(acc0[0], acc0[1]);
            *(float2*)&sg[(g * 4 + b) * 32 + jb + 8] = make_float2(acc1[0], acc1[1]);
        }
        __syncthreads();

        float h = 0.f;
        if (tid < 128) {
            gi += sg[(0 * 4 + fb) * 32 + fn];
            gf += sg[(1 * 4 + fb) * 32 + fn];
            gg += sg[(2 * 4 + fb) * 32 + fn];
            go += sg[(3 * 4 + fb) * 32 + fn];
            float iv = 1.f / (1.f + expf(-gi));
            float fv = 1.f / (1.f + expf(-gf));
            float gv = tanhf(gg);
            float ov = 1.f / (1.f + expf(-go));
            cS = fv * cS + iv * gv;
            h = ov * tanhf(cS);

            unsigned short hu = __half_as_ushort(__float2half(h));
#pragma unroll
            for (int r = 0; r < 8; r++) {
                uint32_t ra = p ? remA[r] : remB[r];   // write buffer p^1
                asm volatile("st.shared::cluster.u16 [%0], %1;" :: "r"(ra), "h"(hu) : "memory");
            }
        }

        asm volatile("barrier.cluster.arrive.aligned;" ::: "memory");
        if (tid < 128) {
            if (ysh) ysh[row * 256 + n0 + fn] = __float2half(h);
            if (step == nSteps - 1) {
                if (hFin) hFin[bG * 256 + n0 + fn] = h;
                if (cFin) cFin[bG * 256 + n0 + fn] = cS;
            }
        }
        asm volatile("barrier.cluster.wait.aligned;" ::: "memory");
        p ^= 1;
    }
}

// ---------------- host launch ----------------
extern "C" void kernel_launch(void* const* d_in, const int* in_sizes, int n_in,
                              void* d_out, int out_size) {
    const int*   src     = (const int*)d_in[0];
    const int*   trg     = (const int*)d_in[1];
    const float* enc_emb = (const float*)d_in[2];
    const float* dec_emb = (const float*)d_in[3];
    const float* eWih0 = (const float*)d_in[4],  *eWhh0 = (const float*)d_in[5];
    const float* ebih0 = (const float*)d_in[6],  *ebhh0 = (const float*)d_in[7];
    const float* eWih1 = (const float*)d_in[8],  *eWhh1 = (const float*)d_in[9];
    const float* ebih1 = (const float*)d_in[10], *ebhh1 = (const float*)d_in[11];
    const float* dWih0 = (const float*)d_in[12], *dWhh0 = (const float*)d_in[13];
    const float* dbih0 = (const float*)d_in[14], *dbhh0 = (const float*)d_in[15];
    const float* dWih1 = (const float*)d_in[16], *dWhh1 = (const float*)d_in[17];
    const float* dbih1 = (const float*)d_in[18], *dbhh1 = (const float*)d_in[19];
    const float* fcW   = (const float*)d_in[20], *fcb   = (const float*)d_in[21];
    float* out = (float*)d_out;

    float *pxg, *phF, *pcF;
    __half *pxh, *pyh, *pw0, *pw1, *pw2, *pw3, *pfw;
    cudaGetSymbolAddress((void**)&pxg,   g_xg);
    cudaGetSymbolAddress((void**)&phF,   g_hF);
    cudaGetSymbolAddress((void**)&pcF,   g_cF);
    cudaGetSymbolAddress((void**)&pxh,   g_xh);
    cudaGetSymbolAddress((void**)&pyh,   g_yh);
    cudaGetSymbolAddress((void**)&pw0,   g_w0);
    cudaGetSymbolAddress((void**)&pw1,   g_w1);
    cudaGetSymbolAddress((void**)&pw2,   g_w2);
    cudaGetSymbolAddress((void**)&pw3,   g_w3);
    cudaGetSymbolAddress((void**)&pfw,   g_fw);

    cudaFuncSetAttribute(lstm_rec_kernel,
                         cudaFuncAttributeMaxDynamicSharedMemorySize, REC_SMEM_BYTES);
    cudaFuncSetAttribute(gemm16_kernel,
                         cudaFuncAttributeMaxDynamicSharedMemorySize, GSMEM);

    // fused weight conversion + output-row-0 zeroing
    f2h_all_kernel<<<(8978432 / 4 + 255) / 256, 256>>>(eWih0, eWih1, dWih0, dWih1, fcW,
                                                       pw0, pw1, pw2, pw3, pfw);
    zero_first_kernel<<<(NB * NV + 255) / 256, 256>>>(out);

    // ---- Encoder ----
    embed_src_kernel<<<(NSX * NB * NE + 255) / 256, 256>>>(src, enc_emb, pxh);
    gemm16_kernel<<<dim3(16, 64), 256, GSMEM>>>(pxh, pw0, ebih0, ebhh0, pxg,
                                                G4, NE, 0);
    lstm_rec_kernel<<<128, 256, REC_SMEM_BYTES>>>(pxg, eWhh0, nullptr, nullptr,
                                                  pyh, phF, pcF, 128);
    gemm16_kernel<<<dim3(16, 64), 256, GSMEM>>>(pyh, pw1, ebih1, ebhh1, pxg,
                                                G4, NH, 0);
    lstm_rec_kernel<<<128, 256, REC_SMEM_BYTES>>>(pxg, eWhh1, nullptr, nullptr,
                                                  nullptr, phF + NB * NH, pcF + NB * NH,
                                                  128);

    // ---- Decoder (teacher forced) ----
    embed_trg_kernel<<<(127 * NB * NE + 255) / 256, 256>>>(trg, dec_emb, pxh);
    gemm16_kernel<<<dim3(16, 64), 256, GSMEM>>>(pxh, pw2, dbih0, dbhh0, pxg,
                                                G4, NE, 0);
    lstm_rec_kernel<<<128, 256, REC_SMEM_BYTES>>>(pxg, dWhh0, phF, pcF,
                                                  pyh, nullptr, nullptr, 127);
    gemm16_kernel<<<dim3(16, 64), 256, GSMEM>>>(pyh, pw3, dbih1, dbhh1, pxg,
                                                G4, NH, 0);
    lstm_rec_kernel<<<128, 256, REC_SMEM_BYTES>>>(pxg, dWhh1, phF + NB * NH, pcF + NB * NH,
                                                  pyh, nullptr, nullptr, 127);

    // ---- Output: fp16 tensor-core FC over all steps ----
    gemm16_kernel<<<dim3(500, 64), 256, GSMEM>>>(pyh, pfw, fcb, nullptr, out,
                                                 NV, NH, 1);
}